// round 8
// baseline (speedup 1.0000x reference)
#include <cuda_runtime.h>
#include <cuda_bf16.h>
#include <cuda_fp16.h>
#include <math.h>
#include <stdint.h>

// Problem constants
#define NTOK 512
#define DD   128
#define NN   (NTOK*NTOK)

// Scratch (static __device__ arrays — no allocation allowed)
//   g_ab[arr][c][row*512+k] bf16, arr: 0=left-hi 1=left-lo 2=right-hi 3=right-lo
//   g_og  [c][j*512+i] fp16 sigmoid(out-gate)
//   g_mix [d][j*512+i] einsum result f32
//   g_wfrag[w][kc][p][spl][lane] uint4 — B-fragment-ready weights
__device__ __nv_bfloat16 g_ab[134217728];
__device__ __half        g_og [33554432];
__device__ float         g_mix[33554432];
__device__ __align__(16) uint4 g_wfrag[6 * 4096];

#define ARRSZ (128*NN)   // elements per arr slab

// ---------------------------------------------------------------------------
// helpers
// ---------------------------------------------------------------------------
__device__ __forceinline__ uint32_t smem_u32(const void* p) {
    uint32_t a;
    asm("{ .reg .u64 t; cvta.to.shared.u64 t, %1; cvt.u32.u64 %0, t; }"
        : "=r"(a) : "l"(p));
    return a;
}

__device__ __forceinline__ void ldm4(uint32_t r[4], uint32_t addr) {
    asm volatile("ldmatrix.sync.aligned.m8n8.x4.shared.b16 {%0,%1,%2,%3}, [%4];"
                 : "=r"(r[0]), "=r"(r[1]), "=r"(r[2]), "=r"(r[3]) : "r"(addr));
}

__device__ __forceinline__ void mma_bf16(float acc[4], const uint32_t a[4],
                                         uint32_t b0, uint32_t b1) {
    asm volatile(
        "mma.sync.aligned.m16n8k16.row.col.f32.bf16.bf16.f32 "
        "{%0,%1,%2,%3}, {%4,%5,%6,%7}, {%8,%9}, {%0,%1,%2,%3};"
        : "+f"(acc[0]), "+f"(acc[1]), "+f"(acc[2]), "+f"(acc[3])
        : "r"(a[0]), "r"(a[1]), "r"(a[2]), "r"(a[3]), "r"(b0), "r"(b1));
}

#define CPASYNC16(dst, src) \
    asm volatile("cp.async.cg.shared.global [%0], [%1], 16;" \
                 :: "r"(dst), "l"(src) : "memory")
#define CPCOMMIT() asm volatile("cp.async.commit_group;" ::: "memory")
#define CPWAIT1()  asm volatile("cp.async.wait_group 1;" ::: "memory")
#define CPWAIT0()  asm volatile("cp.async.wait_group 0;" ::: "memory")

__device__ __forceinline__ float sigmoidf_(float z) {
    return 1.f / (1.f + expf(-z));
}

__device__ __forceinline__ uint32_t split_pack(float v) {
    __nv_bfloat16 h = __float2bfloat16(v);
    __nv_bfloat16 l = __float2bfloat16(v - __bfloat162float(h));
    uint16_t hu = *(uint16_t*)&h, lu = *(uint16_t*)&l;
    return (uint32_t)hu | ((uint32_t)lu << 16);
}

// ---------------------------------------------------------------------------
// Kernel 0: weights -> B-fragment layout (hi/lo), register-ready for mma.sync.
// ---------------------------------------------------------------------------
__global__ void wprep_kernel(const float* __restrict__ W0, const float* __restrict__ W1,
                             const float* __restrict__ W2, const float* __restrict__ W3,
                             const float* __restrict__ W4, const float* __restrict__ W5)
{
    const float* W = (blockIdx.x == 0) ? W0 : (blockIdx.x == 1) ? W1 :
                     (blockIdx.x == 2) ? W2 : (blockIdx.x == 3) ? W3 :
                     (blockIdx.x == 4) ? W4 : W5;
    uint4* dst = g_wfrag + blockIdx.x * 4096;
    for (int idx = threadIdx.x; idx < 4096; idx += 256) {
        const int lane = idx & 31;
        const int spl  = (idx >> 5) & 1;
        const int p    = (idx >> 6) & 7;
        const int kc   = idx >> 9;
        const int nf = p * 16 + (lane >> 2);
        const int k0 = kc * 16 + 2 * (lane & 3);
        uint16_t e[8];
        #pragma unroll
        for (int q = 0; q < 8; ++q) {
            const int k = k0 + (q & 1) + ((q >> 1) & 1) * 8;
            const int n = nf + (q >> 2) * 8;
            const float v = W[k * 128 + n];
            __nv_bfloat16 h = __float2bfloat16(v);
            __nv_bfloat16 l = __float2bfloat16(v - __bfloat162float(h));
            e[q] = spl ? *(uint16_t*)&l : *(uint16_t*)&h;
        }
        uint4 o;
        o.x = (uint32_t)e[0] | ((uint32_t)e[1] << 16);
        o.y = (uint32_t)e[2] | ((uint32_t)e[3] << 16);
        o.z = (uint32_t)e[4] | ((uint32_t)e[5] << 16);
        o.w = (uint32_t)e[6] | ((uint32_t)e[7] << 16);
        dst[idx] = o;
    }
}

// ---------------------------------------------------------------------------
// Kernel 1: LayerNorm + 5 projections as FIVE thin passes (32 acc regs each)
// -> 3 CTAs/SM. Gate pass stages sigmoid in smem; value pass combines
// in-thread (same slot mapping -> no sync between gate and value pass).
// ---------------------------------------------------------------------------
#define K1_AH   0
#define K1_AL   17408
#define K1_ST   34816          // 64 x 129 f32/u32 = 33024
#define K1_MS   67840          // 64 f32
#define K1_SMEM 68096

// MODE: 0 = gate (stage sigmoid f32), 1 = value (combine+pack), 2 = out-gate
template<int MODE>
__device__ __forceinline__ void k1_thin(
    char* sm1, uint32_t sb, int w, const float* __restrict__ bias,
    int lane, int wm, int wn)
{
    const int g = lane >> 3, r = lane & 7;
    uint32_t aoffH[2], aoffL[2];
    #pragma unroll
    for (int mi = 0; mi < 2; ++mi) {
        const uint32_t base = (uint32_t)((wm + mi*16 + r + (g&1)*8) * 272 + ((g>>1)*8)*2);
        aoffH[mi] = sb + K1_AH + base;
        aoffL[mi] = sb + K1_AL + base;
    }
    const uint4* __restrict__ fw = g_wfrag + w * 4096 + lane;
    const int pbase = wn >> 4;

    float acc[2][4][4] = {};
    #pragma unroll
    for (int kc = 0; kc < 8; ++kc) {
        uint32_t AH[2][4], AL[2][4];
        #pragma unroll
        for (int mi = 0; mi < 2; ++mi) {
            ldm4(AH[mi], aoffH[mi] + kc*32);
            ldm4(AL[mi], aoffL[mi] + kc*32);
        }
        #pragma unroll
        for (int p4 = 0; p4 < 2; ++p4) {
            const int fidx = ((kc*8 + pbase + p4) * 2) * 32;
            const uint4 bh = fw[fidx];
            const uint4 bl = fw[fidx + 32];
            #pragma unroll
            for (int ns = 0; ns < 2; ++ns) {
                const int ni = p4*2 + ns;
                const uint32_t h0 = ns ? bh.z : bh.x, h1 = ns ? bh.w : bh.y;
                const uint32_t l0 = ns ? bl.z : bl.x, l1 = ns ? bl.w : bl.y;
                #pragma unroll
                for (int mi = 0; mi < 2; ++mi) {
                    mma_bf16(acc[mi][ni], AH[mi], h0, h1);
                    mma_bf16(acc[mi][ni], AH[mi], l0, l1);
                    mma_bf16(acc[mi][ni], AL[mi], h0, h1);
                }
            }
        }
    }

    float*    stagef = (float*)(sm1 + K1_ST);
    uint32_t* stageu = (uint32_t*)(sm1 + K1_ST);
    const float* mask_s = (const float*)(sm1 + K1_MS);

    #pragma unroll
    for (int mi = 0; mi < 2; ++mi)
        #pragma unroll
        for (int ni = 0; ni < 4; ++ni) {
            const int m0 = wm + mi*16 + (lane >> 2);
            const int n  = wn + ni*8 + (lane & 3)*2;
            const float b0 = __ldg(bias + n), b1 = __ldg(bias + n + 1);
            float* a = acc[mi][ni];
            if (MODE == 1) {
                const float mk0 = mask_s[m0], mk1 = mask_s[m0 + 8];
                const float g00 = stagef[ m0   *129 + n    ];
                const float g01 = stagef[ m0   *129 + n + 1];
                const float g10 = stagef[(m0+8)*129 + n    ];
                const float g11 = stagef[(m0+8)*129 + n + 1];
                stageu[ m0   *129 + n    ] = split_pack((a[0]+b0)*mk0*g00);
                stageu[ m0   *129 + n + 1] = split_pack((a[1]+b1)*mk0*g01);
                stageu[(m0+8)*129 + n    ] = split_pack((a[2]+b0)*mk1*g10);
                stageu[(m0+8)*129 + n + 1] = split_pack((a[3]+b1)*mk1*g11);
            } else {
                stagef[ m0   *129 + n    ] = sigmoidf_(a[0] + b0);
                stagef[ m0   *129 + n + 1] = sigmoidf_(a[1] + b1);
                stagef[(m0+8)*129 + n    ] = sigmoidf_(a[2] + b0);
                stagef[(m0+8)*129 + n + 1] = sigmoidf_(a[3] + b1);
            }
        }
}

__global__ __launch_bounds__(256, 3) void ln_proj_mma_kernel(
    const float* __restrict__ x,   const float* __restrict__ msk,
    const float* __restrict__ nsc, const float* __restrict__ nbi,
    const float* __restrict__ bl,  const float* __restrict__ br,
    const float* __restrict__ blg, const float* __restrict__ brg,
    const float* __restrict__ bog)
{
    extern __shared__ __align__(16) char sm1[];
    const int tid  = threadIdx.x;
    const int lane = tid & 31;
    const int wid  = tid >> 5;
    const int n2   = blockIdx.x & 511;
    const int n1b  = (blockIdx.x >> 9) << 6;
    const uint32_t sb = smem_u32(sm1);

    // ---- LayerNorm prologue: write bf16 hi/lo A into smem ----
    {
        const int row = tid >> 2, sub = tid & 3;
        const float4* xr = reinterpret_cast<const float4*>(
                               x + ((size_t)(n1b + row) * 512 + n2) * DD) + sub * 8;
        float4 v[8];
        float s = 0.f, ss = 0.f;
        #pragma unroll
        for (int q = 0; q < 8; ++q) {
            v[q] = xr[q];
            s  += v[q].x + v[q].y + v[q].z + v[q].w;
            ss += v[q].x*v[q].x + v[q].y*v[q].y + v[q].z*v[q].z + v[q].w*v[q].w;
        }
        s  += __shfl_xor_sync(0xffffffffu, s, 1);
        ss += __shfl_xor_sync(0xffffffffu, ss, 1);
        s  += __shfl_xor_sync(0xffffffffu, s, 2);
        ss += __shfl_xor_sync(0xffffffffu, ss, 2);
        const float mu   = s * (1.f/128.f);
        const float var  = ss * (1.f/128.f) - mu*mu;
        const float rstd = rsqrtf(var + 1e-6f);
        #pragma unroll
        for (int q = 0; q < 8; ++q) {
            const int d0 = sub*32 + q*4;
            float a0 = (v[q].x - mu)*rstd*__ldg(&nsc[d0+0]) + __ldg(&nbi[d0+0]);
            float a1 = (v[q].y - mu)*rstd*__ldg(&nsc[d0+1]) + __ldg(&nbi[d0+1]);
            float a2 = (v[q].z - mu)*rstd*__ldg(&nsc[d0+2]) + __ldg(&nbi[d0+2]);
            float a3 = (v[q].w - mu)*rstd*__ldg(&nsc[d0+3]) + __ldg(&nbi[d0+3]);
            uint32_t p0 = split_pack(a0), p1 = split_pack(a1);
            uint32_t p2 = split_pack(a2), p3 = split_pack(a3);
            uint2 hw, lw;
            hw.x = (p0 & 0xffffu) | (p1 << 16);
            hw.y = (p2 & 0xffffu) | (p3 << 16);
            lw.x = (p0 >> 16) | (p1 & 0xffff0000u);
            lw.y = (p2 >> 16) | (p3 & 0xffff0000u);
            *(uint2*)(sm1 + K1_AH + row*272 + d0*2) = hw;
            *(uint2*)(sm1 + K1_AL + row*272 + d0*2) = lw;
        }
        if (sub == 0)
            ((float*)(sm1 + K1_MS))[row] = msk[n1b + row] * msk[n2];
    }
    __syncthreads();

    const int wm = (wid & 1) * 32;
    const int wn = (wid >> 1) * 32;
    const size_t gbase = (size_t)n2 * 512 + n1b;
    uint32_t* stageu = (uint32_t*)(sm1 + K1_ST);
    float*    stagef = (float*)(sm1 + K1_ST);

    // ---- left: gate then value (no sync needed between) ----
    k1_thin<0>(sm1, sb, 0, blg, lane, wm, wn);
    k1_thin<1>(sm1, sb, 1, bl,  lane, wm, wn);
    __syncthreads();
    #pragma unroll
    for (int it = 0; it < 16; ++it) {
        const int idx = it * 256 + tid;
        const int c  = idx >> 5;
        const int rp = (idx & 31) * 2;
        const uint32_t u0 = stageu[ rp      * 129 + c];
        const uint32_t u1 = stageu[(rp + 1) * 129 + c];
        const size_t off = (size_t)c * NN + gbase + rp;
        *(uint32_t*)(g_ab + off)         = (u0 & 0xffffu) | (u1 << 16);
        *(uint32_t*)(g_ab + ARRSZ + off) = (u0 >> 16) | (u1 & 0xffff0000u);
    }
    __syncthreads();

    // ---- right: gate then value ----
    k1_thin<0>(sm1, sb, 2, brg, lane, wm, wn);
    k1_thin<1>(sm1, sb, 3, br,  lane, wm, wn);
    __syncthreads();
    #pragma unroll
    for (int it = 0; it < 16; ++it) {
        const int idx = it * 256 + tid;
        const int c  = idx >> 5;
        const int rp = (idx & 31) * 2;
        const uint32_t u0 = stageu[ rp      * 129 + c];
        const uint32_t u1 = stageu[(rp + 1) * 129 + c];
        const size_t off = (size_t)c * NN + gbase + rp;
        *(uint32_t*)(g_ab + 2*ARRSZ + off) = (u0 & 0xffffu) | (u1 << 16);
        *(uint32_t*)(g_ab + 3*ARRSZ + off) = (u0 >> 16) | (u1 & 0xffff0000u);
    }
    __syncthreads();

    // ---- out-gate ----
    k1_thin<2>(sm1, sb, 4, bog, lane, wm, wn);
    __syncthreads();
    #pragma unroll
    for (int it = 0; it < 16; ++it) {
        const int idx = it * 256 + tid;
        const int c  = idx >> 5;
        const int rp = (idx & 31) * 2;
        __half2 h2 = __floats2half2_rn(stagef[rp*129 + c], stagef[(rp+1)*129 + c]);
        *(__half2*)(g_og + (size_t)c * NN + gbase + rp) = h2;
    }
}

// ---------------------------------------------------------------------------
// Kernel 2: einsum via mma.sync bf16 (3-MMA split). 128x64 tiles, cp.async
// double-buffered stages, 2 CTAs/SM.
// ---------------------------------------------------------------------------
#define E2_STAGE 30720
#define E2_SMEM  61440

__global__ __launch_bounds__(256, 2) void einsum_mma_kernel()
{
    extern __shared__ __align__(16) char esm[];
    const int tid  = threadIdx.x;
    const int lane = tid & 31;
    const int wid  = tid >> 5;
    const int d    = blockIdx.y;
    const int i0   = (blockIdx.x & 3) * 128;
    const int j0   = (blockIdx.x >> 2) * 64;
    const uint32_t sbm = smem_u32(esm);

    const __nv_bfloat16* __restrict__ base = g_ab + (size_t)d * NN;

    // 6 transfers per chunk: AH 2x256thr, AL 2x256thr, BH 1, BL 1 (16B each)
    uint32_t goff[6], soff[6];
    #pragma unroll
    for (int it = 0; it < 6; ++it) {
        int arr, rem;
        if (it < 4) { arr = it >> 1; rem = (it & 1) * 256 + tid; }
        else        { arr = it - 2;  rem = tid; }
        const int row = rem >> 2, seg = rem & 3;
        const int r0 = (arr < 2) ? i0 : j0;
        const uint32_t ab = (arr == 0) ? 0u : (arr == 1) ? 10240u :
                            (arr == 2) ? 20480u : 25600u;
        goff[it] = (uint32_t)(arr * ARRSZ) + (uint32_t)((r0 + row)*512 + seg*8);
        soff[it] = ab + (uint32_t)(row*80 + seg*16);
    }

    const int g = lane >> 3, r = lane & 7;
    const int wm = (wid & 3) * 32;
    const int wn = (wid >> 2) * 32;
    uint32_t aoff[2][2], boff[2][2];
    #pragma unroll
    for (int mi = 0; mi < 2; ++mi) {
        const uint32_t bse = (uint32_t)((wm + mi*16 + r + (g&1)*8)*80 + ((g>>1)*8)*2);
        aoff[0][mi] = sbm + bse;
        aoff[1][mi] = sbm + 10240 + bse;
    }
    #pragma unroll
    for (int p = 0; p < 2; ++p) {
        const uint32_t bse = (uint32_t)((wn + p*16 + r + (g>>1)*8)*80 + ((g&1)*8)*2);
        boff[0][p] = sbm + 20480 + bse;
        boff[1][p] = sbm + 25600 + bse;
    }

    float acc[2][4][4] = {};

    // prologue: chunk 0 -> stage 0
    #pragma unroll
    for (int it = 0; it < 6; ++it)
        CPASYNC16(sbm + soff[it], base + goff[it]);
    CPCOMMIT();

    #pragma unroll 1
    for (int kc = 0; kc < 16; ++kc) {
        const uint32_t stg = (uint32_t)(kc & 1) * E2_STAGE;
        if (kc < 15) {
            const uint32_t nstg = (uint32_t)((kc + 1) & 1) * E2_STAGE;
            const int kb = (kc + 1) * 32;
            #pragma unroll
            for (int it = 0; it < 6; ++it)
                CPASYNC16(sbm + nstg + soff[it], base + goff[it] + kb);
            CPCOMMIT();
            CPWAIT1();
        } else {
            CPWAIT0();
        }
        __syncthreads();

        #pragma unroll
        for (int ks2 = 0; ks2 < 2; ++ks2) {
            const uint32_t off = stg + (uint32_t)ks2 * 32;
            uint32_t AH[2][4], AL[2][4], BH[2][4], BL[2][4];
            #pragma unroll
            for (int mi = 0; mi < 2; ++mi) {
                ldm4(AH[mi], aoff[0][mi] + off);
                ldm4(AL[mi], aoff[1][mi] + off);
            }
            #pragma unroll
            for (int p = 0; p < 2; ++p) {
                ldm4(BH[p], boff[0][p] + off);
                ldm4(BL[p], boff[1][p] + off);
            }
            #pragma unroll
            for (int mi = 0; mi < 2; ++mi)
                #pragma unroll
                for (int ni = 0; ni < 4; ++ni) {
                    const int p = ni >> 1, h = (ni & 1) * 2;
                    mma_bf16(acc[mi][ni], AH[mi], BH[p][h], BH[p][h+1]);
                    mma_bf16(acc[mi][ni], AH[mi], BL[p][h], BL[p][h+1]);
                    mma_bf16(acc[mi][ni], AL[mi], BH[p][h], BH[p][h+1]);
                }
        }
        __syncthreads();   // all warps done with stage stg before next cp.async overwrites
    }

    float* smT = (float*)esm;   // [64][132]
    #pragma unroll
    for (int mi = 0; mi < 2; ++mi)
        #pragma unroll
        for (int ni = 0; ni < 4; ++ni) {
            const int m = wm + mi*16 + (lane >> 2);
            const int j = wn + ni*8 + (lane & 3)*2;
            smT[(j  )*132 + m    ] = acc[mi][ni][0];
            smT[(j+1)*132 + m    ] = acc[mi][ni][1];
            smT[(j  )*132 + m + 8] = acc[mi][ni][2];
            smT[(j+1)*132 + m + 8] = acc[mi][ni][3];
        }
    __syncthreads();

    float* gm = g_mix + (size_t)d * NN;
    #pragma unroll
    for (int it = 0; it < 8; ++it) {
        const int idx = it*256 + tid;
        const int j = idx >> 5, c4 = idx & 31;
        float4 o;
        o.x = smT[j*132 + c4*4 + 0];
        o.y = smT[j*132 + c4*4 + 1];
        o.z = smT[j*132 + c4*4 + 2];
        o.w = smT[j*132 + c4*4 + 3];
        *reinterpret_cast<float4*>(gm + (size_t)(j0 + j)*512 + i0 + c4*4) = o;
    }
}

// ---------------------------------------------------------------------------
// Kernel 3: out-LN (over d) * out_gate, then @ W_out + b_out — MMA version.
// ---------------------------------------------------------------------------
#define O_MIX   0
#define O_AH    34816
#define O_AL    52224
#define O_RED   69632
#define O_SMEM  71680

__global__ __launch_bounds__(256, 3) void out_mma_kernel(
    const float* __restrict__ gs, const float* __restrict__ gb,
    const float* __restrict__ bout, float* __restrict__ out)
{
    extern __shared__ __align__(16) char sm3[];
    const int tid  = threadIdx.x;
    const int lane = tid & 31;
    const int wid  = tid >> 5;
    const int rt0  = blockIdx.x * 64;
    const int j    = rt0 >> 9;
    const int ibase = rt0 & 511;
    const uint32_t sb = smem_u32(sm3);

    float* mixbuf = (float*)(sm3 + O_MIX);
    float* red    = (float*)(sm3 + O_RED);

    const int rt_l = tid & 63;
    const int qtr  = tid >> 6;
    const int d0   = qtr * 32;

    float s = 0.f, q = 0.f;
    #pragma unroll 8
    for (int dd = d0; dd < d0 + 32; ++dd) {
        float v = g_mix[(size_t)dd*NN + rt0 + rt_l];
        mixbuf[dd*68 + rt_l] = v;
        s += v; q += v*v;
    }
    red[qtr*64 + rt_l]       = s;
    red[256 + qtr*64 + rt_l] = q;
    __syncthreads();
    const float S = red[rt_l] + red[64 + rt_l] + red[128 + rt_l] + red[192 + rt_l];
    const float Q = red[256 + rt_l] + red[320 + rt_l] + red[384 + rt_l] + red[448 + rt_l];
    const float mu   = S * (1.f/128.f);
    const float rstd = rsqrtf(Q * (1.f/128.f) - mu*mu + 1e-6f);

    #pragma unroll 4
    for (int dd = d0; dd < d0 + 32; dd += 2) {
        float v0 = mixbuf[ dd     *68 + rt_l];
        float v1 = mixbuf[(dd + 1)*68 + rt_l];
        float o0 = __half2float(g_og[(size_t) dd     *NN + rt0 + rt_l]);
        float o1 = __half2float(g_og[(size_t)(dd + 1)*NN + rt0 + rt_l]);
        float g0 = ((v0 - mu)*rstd*__ldg(gs+dd)   + __ldg(gb+dd))   * o0;
        float g1 = ((v1 - mu)*rstd*__ldg(gs+dd+1) + __ldg(gb+dd+1)) * o1;
        uint32_t p0 = split_pack(g0), p1 = split_pack(g1);
        *(uint32_t*)(sm3 + O_AH + rt_l*272 + dd*2) = (p0 & 0xffffu) | (p1 << 16);
        *(uint32_t*)(sm3 + O_AL + rt_l*272 + dd*2) = (p0 >> 16) | (p1 & 0xffff0000u);
    }
    __syncthreads();

    const int g = lane >> 3, r = lane & 7;
    const int wm = (wid & 1) * 32;
    const int wn = (wid >> 1) * 32;
    uint32_t aoffH[2], aoffL[2];
    #pragma unroll
    for (int mi = 0; mi < 2; ++mi) {
        const uint32_t bse = (uint32_t)((wm + mi*16 + r + (g&1)*8) * 272 + ((g>>1)*8)*2);
        aoffH[mi] = sb + O_AH + bse;
        aoffL[mi] = sb + O_AL + bse;
    }
    const uint4* __restrict__ fw = g_wfrag + 5 * 4096 + lane;
    const int pbase = wn >> 4;

    float acc[2][4][4] = {};
    #pragma unroll
    for (int kc = 0; kc < 8; ++kc) {
        uint32_t AH[2][4], AL[2][4];
        #pragma unroll
        for (int mi = 0; mi < 2; ++mi) {
            ldm4(AH[mi], aoffH[mi] + kc*32);
            ldm4(AL[mi], aoffL[mi] + kc*32);
        }
        #pragma unroll
        for (int p4 = 0; p4 < 2; ++p4) {
            const int fidx = ((kc*8 + pbase + p4) * 2) * 32;
            const uint4 bh = fw[fidx];
            const uint4 bl = fw[fidx + 32];
            #pragma unroll
            for (int ns = 0; ns < 2; ++ns) {
                const int ni = p4*2 + ns;
                const uint32_t h0 = ns ? bh.z : bh.x, h1 = ns ? bh.w : bh.y;
                const uint32_t l0 = ns ? bl.z : bl.x, l1 = ns ? bl.w : bl.y;
                #pragma unroll
                for (int mi = 0; mi < 2; ++mi) {
                    mma_bf16(acc[mi][ni], AH[mi], h0, h1);
                    mma_bf16(acc[mi][ni], AH[mi], l0, l1);
                    mma_bf16(acc[mi][ni], AL[mi], h0, h1);
                }
            }
        }
    }
    __syncthreads();

    float* stagef = mixbuf;   // reuse as [64][132]
    #pragma unroll
    for (int mi = 0; mi < 2; ++mi)
        #pragma unroll
        for (int ni = 0; ni < 4; ++ni) {
            const int m0 = wm + mi*16 + (lane >> 2);
            const int n  = wn + ni*8 + (lane & 3)*2;
            const float b0 = __ldg(bout + n), b1 = __ldg(bout + n + 1);
            stagef[ m0   *132 + n    ] = acc[mi][ni][0] + b0;
            stagef[ m0   *132 + n + 1] = acc[mi][ni][1] + b1;
            stagef[(m0+8)*132 + n    ] = acc[mi][ni][2] + b0;
            stagef[(m0+8)*132 + n + 1] = acc[mi][ni][3] + b1;
        }
    __syncthreads();

    #pragma unroll
    for (int it = 0; it < 8; ++it) {
        const int idx = it * 256 + tid;
        const int row = idx >> 5, c4 = idx & 31;
        float4 v;
        v.x = stagef[row*132 + c4*4 + 0];
        v.y = stagef[row*132 + c4*4 + 1];
        v.z = stagef[row*132 + c4*4 + 2];
        v.w = stagef[row*132 + c4*4 + 3];
        *reinterpret_cast<float4*>(
            out + ((size_t)(ibase + row)*512 + j)*DD + c4*4) = v;
    }
}

// ---------------------------------------------------------------------------
extern "C" void kernel_launch(void* const* d_in, const int* in_sizes, int n_in,
                              void* d_out, int out_size)
{
    const float* x    = (const float*)d_in[0];
    const float* mskp = (const float*)d_in[1];
    const float* nsc  = (const float*)d_in[2];
    const float* nbi  = (const float*)d_in[3];
    const float* Wl   = (const float*)d_in[4];
    const float* bl   = (const float*)d_in[5];
    const float* Wr   = (const float*)d_in[6];
    const float* br   = (const float*)d_in[7];
    const float* Wlg  = (const float*)d_in[8];
    const float* blg  = (const float*)d_in[9];
    const float* Wrg  = (const float*)d_in[10];
    const float* brg  = (const float*)d_in[11];
    const float* Wog  = (const float*)d_in[12];
    const float* bog  = (const float*)d_in[13];
    const float* gs   = (const float*)d_in[14];
    const float* gb   = (const float*)d_in[15];
    const float* Wout = (const float*)d_in[16];
    const float* bout = (const float*)d_in[17];
    float* out = (float*)d_out;

    cudaFuncSetAttribute(einsum_mma_kernel,
                         cudaFuncAttributeMaxDynamicSharedMemorySize, E2_SMEM);
    cudaFuncSetAttribute(ln_proj_mma_kernel,
                         cudaFuncAttributeMaxDynamicSharedMemorySize, K1_SMEM);
    cudaFuncSetAttribute(out_mma_kernel,
                         cudaFuncAttributeMaxDynamicSharedMemorySize, O_SMEM);

    wprep_kernel<<<6, 256>>>(Wlg, Wl, Wrg, Wr, Wog, Wout);
    ln_proj_mma_kernel<<<4096, 256, K1_SMEM>>>(x, mskp, nsc, nbi,
                                               bl, br, blg, brg, bog);
    einsum_mma_kernel<<<dim3(32, 128), 256, E2_SMEM>>>();
    out_mma_kernel<<<4096, 256, O_SMEM>>>(gs, gb, bout, out);
}

// round 9
// speedup vs baseline: 1.1717x; 1.1717x over previous
#include <cuda_runtime.h>
#include <cuda_bf16.h>
#include <cuda_fp16.h>
#include <math.h>
#include <stdint.h>

// Problem constants
#define NTOK 512
#define DD   128
#define NN   (NTOK*NTOK)

// Scratch (static __device__ arrays — no allocation allowed)
//   g_ab[arr][c][row*512+k] bf16, arr: 0=left-hi 1=left-lo 2=right-hi 3=right-lo
//   g_og  [c][j*512+i] fp16 sigmoid(out-gate)
//   g_mix [d][j*512+i] einsum result f32
//   g_wfrag[w][kc][p][spl][lane] uint4 — B-fragment-ready weights
__device__ __nv_bfloat16 g_ab[134217728];
__device__ __half        g_og [33554432];
__device__ float         g_mix[33554432];
__device__ __align__(16) uint4 g_wfrag[6 * 4096];

#define ARRSZ (128*NN)

// ---------------------------------------------------------------------------
// helpers
// ---------------------------------------------------------------------------
__device__ __forceinline__ uint32_t smem_u32(const void* p) {
    uint32_t a;
    asm("{ .reg .u64 t; cvta.to.shared.u64 t, %1; cvt.u32.u64 %0, t; }"
        : "=r"(a) : "l"(p));
    return a;
}

__device__ __forceinline__ void ldm4(uint32_t r[4], uint32_t addr) {
    asm volatile("ldmatrix.sync.aligned.m8n8.x4.shared.b16 {%0,%1,%2,%3}, [%4];"
                 : "=r"(r[0]), "=r"(r[1]), "=r"(r[2]), "=r"(r[3]) : "r"(addr));
}

__device__ __forceinline__ void mma_bf16(float acc[4], const uint32_t a[4],
                                         uint32_t b0, uint32_t b1) {
    asm volatile(
        "mma.sync.aligned.m16n8k16.row.col.f32.bf16.bf16.f32 "
        "{%0,%1,%2,%3}, {%4,%5,%6,%7}, {%8,%9}, {%0,%1,%2,%3};"
        : "+f"(acc[0]), "+f"(acc[1]), "+f"(acc[2]), "+f"(acc[3])
        : "r"(a[0]), "r"(a[1]), "r"(a[2]), "r"(a[3]), "r"(b0), "r"(b1));
}

#define CPASYNC16(dst, src) \
    asm volatile("cp.async.cg.shared.global [%0], [%1], 16;" \
                 :: "r"(dst), "l"(src) : "memory")
#define CPCOMMIT() asm volatile("cp.async.commit_group;" ::: "memory")
#define CPWAIT1()  asm volatile("cp.async.wait_group 1;" ::: "memory")
#define CPWAIT0()  asm volatile("cp.async.wait_group 0;" ::: "memory")

__device__ __forceinline__ float sigmoidf_(float z) {
    return 1.f / (1.f + expf(-z));
}

__device__ __forceinline__ uint32_t split_pack(float v) {
    __nv_bfloat16 h = __float2bfloat16(v);
    __nv_bfloat16 l = __float2bfloat16(v - __bfloat162float(h));
    uint16_t hu = *(uint16_t*)&h, lu = *(uint16_t*)&l;
    return (uint32_t)hu | ((uint32_t)lu << 16);
}

// ---------------------------------------------------------------------------
// Kernel 0: weights -> B-fragment layout (hi/lo), register-ready for mma.sync.
// ---------------------------------------------------------------------------
__global__ void wprep_kernel(const float* __restrict__ W0, const float* __restrict__ W1,
                             const float* __restrict__ W2, const float* __restrict__ W3,
                             const float* __restrict__ W4, const float* __restrict__ W5)
{
    const float* W = (blockIdx.x == 0) ? W0 : (blockIdx.x == 1) ? W1 :
                     (blockIdx.x == 2) ? W2 : (blockIdx.x == 3) ? W3 :
                     (blockIdx.x == 4) ? W4 : W5;
    uint4* dst = g_wfrag + blockIdx.x * 4096;
    for (int idx = threadIdx.x; idx < 4096; idx += 256) {
        const int lane = idx & 31;
        const int spl  = (idx >> 5) & 1;
        const int p    = (idx >> 6) & 7;
        const int kc   = idx >> 9;
        const int nf = p * 16 + (lane >> 2);
        const int k0 = kc * 16 + 2 * (lane & 3);
        uint16_t e[8];
        #pragma unroll
        for (int q = 0; q < 8; ++q) {
            const int k = k0 + (q & 1) + ((q >> 1) & 1) * 8;
            const int n = nf + (q >> 2) * 8;
            const float v = W[k * 128 + n];
            __nv_bfloat16 h = __float2bfloat16(v);
            __nv_bfloat16 l = __float2bfloat16(v - __bfloat162float(h));
            e[q] = spl ? *(uint16_t*)&l : *(uint16_t*)&h;
        }
        uint4 o;
        o.x = (uint32_t)e[0] | ((uint32_t)e[1] << 16);
        o.y = (uint32_t)e[2] | ((uint32_t)e[3] << 16);
        o.z = (uint32_t)e[4] | ((uint32_t)e[5] << 16);
        o.w = (uint32_t)e[6] | ((uint32_t)e[7] << 16);
        dst[idx] = o;
    }
}

// ---------------------------------------------------------------------------
// Kernel 1: LayerNorm + 5 projections (round-7 fused value+gate version).
// 64-row blocks, 8 warps 2m x 4n, 2 CTAs/SM.
// ---------------------------------------------------------------------------
#define K1_AH   0
#define K1_AL   17408
#define K1_ST   34816
#define K1_MS   67840
#define K1_SMEM 68096

template<bool PAIR>
__device__ __forceinline__ void k1_pass2(
    char* sm1, uint32_t sb, int wv, int wg,
    const float* __restrict__ bv, const float* __restrict__ bg,
    int tid, int lane, int wm, int wn,
    __nv_bfloat16* dst_h, __nv_bfloat16* dst_l, __half* dst_og, size_t gbase)
{
    const int g = lane >> 3, r = lane & 7;
    uint32_t aoffH[2], aoffL[2];
    #pragma unroll
    for (int mi = 0; mi < 2; ++mi) {
        const uint32_t base = (uint32_t)((wm + mi*16 + r + (g&1)*8) * 272 + ((g>>1)*8)*2);
        aoffH[mi] = sb + K1_AH + base;
        aoffL[mi] = sb + K1_AL + base;
    }
    const uint4* __restrict__ fv = g_wfrag + wv * 4096 + lane;
    const uint4* __restrict__ fg = g_wfrag + wg * 4096 + lane;
    const int pbase = wn >> 4;

    float accV[2][4][4] = {};
    float accG[PAIR ? 2 : 1][4][4] = {};

    #pragma unroll
    for (int kc = 0; kc < 8; ++kc) {
        uint32_t AH[2][4], AL[2][4];
        #pragma unroll
        for (int mi = 0; mi < 2; ++mi) {
            ldm4(AH[mi], aoffH[mi] + kc*32);
            ldm4(AL[mi], aoffL[mi] + kc*32);
        }
        #pragma unroll
        for (int p4 = 0; p4 < 2; ++p4) {
            const int fidx = ((kc*8 + pbase + p4) * 2) * 32;
            const uint4 bvh = fv[fidx];
            const uint4 bvl = fv[fidx + 32];
            uint4 bgh, bgl;
            if (PAIR) { bgh = fg[fidx]; bgl = fg[fidx + 32]; }
            #pragma unroll
            for (int ns = 0; ns < 2; ++ns) {
                const int ni = p4*2 + ns;
                const uint32_t v0 = ns ? bvh.z : bvh.x, v1 = ns ? bvh.w : bvh.y;
                const uint32_t l0 = ns ? bvl.z : bvl.x, l1 = ns ? bvl.w : bvl.y;
                #pragma unroll
                for (int mi = 0; mi < 2; ++mi) {
                    mma_bf16(accV[mi][ni], AH[mi], v0, v1);
                    mma_bf16(accV[mi][ni], AH[mi], l0, l1);
                    mma_bf16(accV[mi][ni], AL[mi], v0, v1);
                }
                if (PAIR) {
                    const uint32_t g0 = ns ? bgh.z : bgh.x, g1 = ns ? bgh.w : bgh.y;
                    const uint32_t m0 = ns ? bgl.z : bgl.x, m1 = ns ? bgl.w : bgl.y;
                    #pragma unroll
                    for (int mi = 0; mi < 2; ++mi) {
                        mma_bf16(accG[mi][ni], AH[mi], g0, g1);
                        mma_bf16(accG[mi][ni], AH[mi], m0, m1);
                        mma_bf16(accG[mi][ni], AL[mi], g0, g1);
                    }
                }
            }
        }
    }

    float*    stagef = (float*)(sm1 + K1_ST);
    uint32_t* stageu = (uint32_t*)(sm1 + K1_ST);
    const float* mask_s = (const float*)(sm1 + K1_MS);

    #pragma unroll
    for (int mi = 0; mi < 2; ++mi)
        #pragma unroll
        for (int ni = 0; ni < 4; ++ni) {
            const int m0 = wm + mi*16 + (lane >> 2);
            const int n  = wn + ni*8 + (lane & 3)*2;
            const float b0 = __ldg(bv + n), b1 = __ldg(bv + n + 1);
            float* a = accV[mi][ni];
            if (PAIR) {
                const float c0 = __ldg(bg + n), c1 = __ldg(bg + n + 1);
                const float* gacc = accG[mi][ni];
                const float mk0 = mask_s[m0], mk1 = mask_s[m0 + 8];
                stageu[ m0   *129 + n    ] = split_pack((a[0]+b0)*mk0*sigmoidf_(gacc[0]+c0));
                stageu[ m0   *129 + n + 1] = split_pack((a[1]+b1)*mk0*sigmoidf_(gacc[1]+c1));
                stageu[(m0+8)*129 + n    ] = split_pack((a[2]+b0)*mk1*sigmoidf_(gacc[2]+c0));
                stageu[(m0+8)*129 + n + 1] = split_pack((a[3]+b1)*mk1*sigmoidf_(gacc[3]+c1));
            } else {
                stagef[ m0   *129 + n    ] = sigmoidf_(a[0] + b0);
                stagef[ m0   *129 + n + 1] = sigmoidf_(a[1] + b1);
                stagef[(m0+8)*129 + n    ] = sigmoidf_(a[2] + b0);
                stagef[(m0+8)*129 + n + 1] = sigmoidf_(a[3] + b1);
            }
        }
    __syncthreads();

    if (PAIR) {
        #pragma unroll
        for (int it = 0; it < 16; ++it) {
            const int idx = it * 256 + tid;
            const int c  = idx >> 5;
            const int rp = (idx & 31) * 2;
            const uint32_t u0 = stageu[ rp      * 129 + c];
            const uint32_t u1 = stageu[(rp + 1) * 129 + c];
            const size_t addr = (size_t)c * NN + gbase + rp;
            *(uint32_t*)(dst_h + addr) = (u0 & 0xffffu) | (u1 << 16);
            *(uint32_t*)(dst_l + addr) = (u0 >> 16) | (u1 & 0xffff0000u);
        }
    } else {
        #pragma unroll
        for (int it = 0; it < 16; ++it) {
            const int idx = it * 256 + tid;
            const int c  = idx >> 5;
            const int rp = (idx & 31) * 2;
            __half2 h2 = __floats2half2_rn(stagef[rp*129 + c], stagef[(rp+1)*129 + c]);
            *(__half2*)(dst_og + (size_t)c * NN + gbase + rp) = h2;
        }
    }
    __syncthreads();
}

__global__ __launch_bounds__(256, 2) void ln_proj_mma_kernel(
    const float* __restrict__ x,   const float* __restrict__ msk,
    const float* __restrict__ nsc, const float* __restrict__ nbi,
    const float* __restrict__ bl,  const float* __restrict__ br,
    const float* __restrict__ blg, const float* __restrict__ brg,
    const float* __restrict__ bog)
{
    extern __shared__ __align__(16) char sm1[];
    const int tid  = threadIdx.x;
    const int lane = tid & 31;
    const int wid  = tid >> 5;
    const int n2   = blockIdx.x & 511;
    const int n1b  = (blockIdx.x >> 9) << 6;
    const uint32_t sb = smem_u32(sm1);

    {
        const int row = tid >> 2, sub = tid & 3;
        const float4* xr = reinterpret_cast<const float4*>(
                               x + ((size_t)(n1b + row) * 512 + n2) * DD) + sub * 8;
        float4 v[8];
        float s = 0.f, ss = 0.f;
        #pragma unroll
        for (int q = 0; q < 8; ++q) {
            v[q] = xr[q];
            s  += v[q].x + v[q].y + v[q].z + v[q].w;
            ss += v[q].x*v[q].x + v[q].y*v[q].y + v[q].z*v[q].z + v[q].w*v[q].w;
        }
        s  += __shfl_xor_sync(0xffffffffu, s, 1);
        ss += __shfl_xor_sync(0xffffffffu, ss, 1);
        s  += __shfl_xor_sync(0xffffffffu, s, 2);
        ss += __shfl_xor_sync(0xffffffffu, ss, 2);
        const float mu   = s * (1.f/128.f);
        const float var  = ss * (1.f/128.f) - mu*mu;
        const float rstd = rsqrtf(var + 1e-6f);
        #pragma unroll
        for (int q = 0; q < 8; ++q) {
            const int d0 = sub*32 + q*4;
            float a0 = (v[q].x - mu)*rstd*__ldg(&nsc[d0+0]) + __ldg(&nbi[d0+0]);
            float a1 = (v[q].y - mu)*rstd*__ldg(&nsc[d0+1]) + __ldg(&nbi[d0+1]);
            float a2 = (v[q].z - mu)*rstd*__ldg(&nsc[d0+2]) + __ldg(&nbi[d0+2]);
            float a3 = (v[q].w - mu)*rstd*__ldg(&nsc[d0+3]) + __ldg(&nbi[d0+3]);
            uint32_t p0 = split_pack(a0), p1 = split_pack(a1);
            uint32_t p2 = split_pack(a2), p3 = split_pack(a3);
            uint2 hw, lw;
            hw.x = (p0 & 0xffffu) | (p1 << 16);
            hw.y = (p2 & 0xffffu) | (p3 << 16);
            lw.x = (p0 >> 16) | (p1 & 0xffff0000u);
            lw.y = (p2 >> 16) | (p3 & 0xffff0000u);
            *(uint2*)(sm1 + K1_AH + row*272 + d0*2) = hw;
            *(uint2*)(sm1 + K1_AL + row*272 + d0*2) = lw;
        }
        if (sub == 0)
            ((float*)(sm1 + K1_MS))[row] = msk[n1b + row] * msk[n2];
    }
    __syncthreads();

    const int wm = (wid & 1) * 32;
    const int wn = (wid >> 1) * 32;
    const size_t gbase = (size_t)n2 * 512 + n1b;

    k1_pass2<true >(sm1, sb, 1, 0, bl,  blg, tid, lane, wm, wn,
                    g_ab, g_ab + ARRSZ, 0, gbase);
    k1_pass2<true >(sm1, sb, 3, 2, br,  brg, tid, lane, wm, wn,
                    g_ab + 2*(size_t)ARRSZ, g_ab + 3*(size_t)ARRSZ, 0, gbase);
    k1_pass2<false>(sm1, sb, 4, 4, bog, bog, tid, lane, wm, wn, 0, 0, g_og, gbase);
}

// ---------------------------------------------------------------------------
// Kernel 2: einsum via mma.sync bf16 (3-MMA split). 128x64 tiles,
// cp.async 3-stage ring, ONE sync per K-iteration, 2 CTAs/SM.
// Per iter kc: wait(load kc) -> sync -> issue load(kc+2) -> compute stage kc.
// The sync proves all warps finished compute(kc-1) = the stage load(kc+2)
// overwrites ((kc+2)%3 == (kc-1)%3). Hazard-free with a single barrier.
// ---------------------------------------------------------------------------
#define E3_STAGE 30720
#define E3_SMEM  92160

__global__ __launch_bounds__(256, 2) void einsum_mma_kernel()
{
    extern __shared__ __align__(16) char esm[];
    const int tid  = threadIdx.x;
    const int lane = tid & 31;
    const int wid  = tid >> 5;
    const int d    = blockIdx.y;
    const int i0   = (blockIdx.x & 3) * 128;
    const int j0   = (blockIdx.x >> 2) * 64;
    const uint32_t sbm = smem_u32(esm);

    const __nv_bfloat16* __restrict__ base = g_ab + (size_t)d * NN;

    uint32_t goff[6], soff[6];
    #pragma unroll
    for (int it = 0; it < 6; ++it) {
        int arr, rem;
        if (it < 4) { arr = it >> 1; rem = (it & 1) * 256 + tid; }
        else        { arr = it - 2;  rem = tid; }
        const int row = rem >> 2, seg = rem & 3;
        const int r0 = (arr < 2) ? i0 : j0;
        const uint32_t ab = (arr == 0) ? 0u : (arr == 1) ? 10240u :
                            (arr == 2) ? 20480u : 25600u;
        goff[it] = (uint32_t)(arr * ARRSZ) + (uint32_t)((r0 + row)*512 + seg*8);
        soff[it] = ab + (uint32_t)(row*80 + seg*16);
    }

    const int g = lane >> 3, r = lane & 7;
    const int wm = (wid & 3) * 32;
    const int wn = (wid >> 2) * 32;
    uint32_t aoff[2][2], boff[2][2];
    #pragma unroll
    for (int mi = 0; mi < 2; ++mi) {
        const uint32_t bse = (uint32_t)((wm + mi*16 + r + (g&1)*8)*80 + ((g>>1)*8)*2);
        aoff[0][mi] = sbm + bse;
        aoff[1][mi] = sbm + 10240 + bse;
    }
    #pragma unroll
    for (int p = 0; p < 2; ++p) {
        const uint32_t bse = (uint32_t)((wn + p*16 + r + (g>>1)*8)*80 + ((g&1)*8)*2);
        boff[0][p] = sbm + 20480 + bse;
        boff[1][p] = sbm + 25600 + bse;
    }

    float acc[2][4][4] = {};

    // prologue: chunks 0 and 1 into stages 0 and 1
    #pragma unroll
    for (int it = 0; it < 6; ++it)
        CPASYNC16(sbm + soff[it], base + goff[it]);
    CPCOMMIT();
    #pragma unroll
    for (int it = 0; it < 6; ++it)
        CPASYNC16(sbm + E3_STAGE + soff[it], base + goff[it] + 32);
    CPCOMMIT();

    #pragma unroll 1
    for (int kc = 0; kc < 16; ++kc) {
        if (kc < 15) { CPWAIT1(); } else { CPWAIT0(); }
        __syncthreads();

        if (kc < 14) {
            const uint32_t nstg = (uint32_t)((kc + 2) % 3) * E3_STAGE;
            const int kb = (kc + 2) * 32;
            #pragma unroll
            for (int it = 0; it < 6; ++it)
                CPASYNC16(sbm + nstg + soff[it], base + goff[it] + kb);
            CPCOMMIT();
        }

        const uint32_t stg = (uint32_t)(kc % 3) * E3_STAGE;
        #pragma unroll
        for (int ks2 = 0; ks2 < 2; ++ks2) {
            const uint32_t off = stg + (uint32_t)ks2 * 32;
            uint32_t AH[2][4], AL[2][4], BH[2][4], BL[2][4];
            #pragma unroll
            for (int mi = 0; mi < 2; ++mi) {
                ldm4(AH[mi], aoff[0][mi] + off);
                ldm4(AL[mi], aoff[1][mi] + off);
            }
            #pragma unroll
            for (int p = 0; p < 2; ++p) {
                ldm4(BH[p], boff[0][p] + off);
                ldm4(BL[p], boff[1][p] + off);
            }
            #pragma unroll
            for (int mi = 0; mi < 2; ++mi)
                #pragma unroll
                for (int ni = 0; ni < 4; ++ni) {
                    const int p = ni >> 1, h = (ni & 1) * 2;
                    mma_bf16(acc[mi][ni], AH[mi], BH[p][h], BH[p][h+1]);
                    mma_bf16(acc[mi][ni], AH[mi], BL[p][h], BL[p][h+1]);
                    mma_bf16(acc[mi][ni], AL[mi], BH[p][h], BH[p][h+1]);
                }
        }
    }
    __syncthreads();

    float* smT = (float*)esm;   // [64][132]
    #pragma unroll
    for (int mi = 0; mi < 2; ++mi)
        #pragma unroll
        for (int ni = 0; ni < 4; ++ni) {
            const int m = wm + mi*16 + (lane >> 2);
            const int j = wn + ni*8 + (lane & 3)*2;
            smT[(j  )*132 + m    ] = acc[mi][ni][0];
            smT[(j+1)*132 + m    ] = acc[mi][ni][1];
            smT[(j  )*132 + m + 8] = acc[mi][ni][2];
            smT[(j+1)*132 + m + 8] = acc[mi][ni][3];
        }
    __syncthreads();

    float* gm = g_mix + (size_t)d * NN;
    #pragma unroll
    for (int it = 0; it < 8; ++it) {
        const int idx = it*256 + tid;
        const int j = idx >> 5, c4 = idx & 31;
        float4 o;
        o.x = smT[j*132 + c4*4 + 0];
        o.y = smT[j*132 + c4*4 + 1];
        o.z = smT[j*132 + c4*4 + 2];
        o.w = smT[j*132 + c4*4 + 3];
        *reinterpret_cast<float4*>(gm + (size_t)(j0 + j)*512 + i0 + c4*4) = o;
    }
}

// ---------------------------------------------------------------------------
// Kernel 3: out-LN (over d) * out_gate, then @ W_out + b_out — MMA version.
// ---------------------------------------------------------------------------
#define O_MIX   0
#define O_AH    34816
#define O_AL    52224
#define O_RED   69632
#define O_SMEM  71680

__global__ __launch_bounds__(256, 3) void out_mma_kernel(
    const float* __restrict__ gs, const float* __restrict__ gb,
    const float* __restrict__ bout, float* __restrict__ out)
{
    extern __shared__ __align__(16) char sm3[];
    const int tid  = threadIdx.x;
    const int lane = tid & 31;
    const int wid  = tid >> 5;
    const int rt0  = blockIdx.x * 64;
    const int j    = rt0 >> 9;
    const int ibase = rt0 & 511;
    const uint32_t sb = smem_u32(sm3);

    float* mixbuf = (float*)(sm3 + O_MIX);
    float* red    = (float*)(sm3 + O_RED);

    const int rt_l = tid & 63;
    const int qtr  = tid >> 6;
    const int d0   = qtr * 32;

    float s = 0.f, q = 0.f;
    #pragma unroll 8
    for (int dd = d0; dd < d0 + 32; ++dd) {
        float v = g_mix[(size_t)dd*NN + rt0 + rt_l];
        mixbuf[dd*68 + rt_l] = v;
        s += v; q += v*v;
    }
    red[qtr*64 + rt_l]       = s;
    red[256 + qtr*64 + rt_l] = q;
    __syncthreads();
    const float S = red[rt_l] + red[64 + rt_l] + red[128 + rt_l] + red[192 + rt_l];
    const float Q = red[256 + rt_l] + red[320 + rt_l] + red[384 + rt_l] + red[448 + rt_l];
    const float mu   = S * (1.f/128.f);
    const float rstd = rsqrtf(Q * (1.f/128.f) - mu*mu + 1e-6f);

    #pragma unroll 4
    for (int dd = d0; dd < d0 + 32; dd += 2) {
        float v0 = mixbuf[ dd     *68 + rt_l];
        float v1 = mixbuf[(dd + 1)*68 + rt_l];
        float o0 = __half2float(g_og[(size_t) dd     *NN + rt0 + rt_l]);
        float o1 = __half2float(g_og[(size_t)(dd + 1)*NN + rt0 + rt_l]);
        float g0 = ((v0 - mu)*rstd*__ldg(gs+dd)   + __ldg(gb+dd))   * o0;
        float g1 = ((v1 - mu)*rstd*__ldg(gs+dd+1) + __ldg(gb+dd+1)) * o1;
        uint32_t p0 = split_pack(g0), p1 = split_pack(g1);
        *(uint32_t*)(sm3 + O_AH + rt_l*272 + dd*2) = (p0 & 0xffffu) | (p1 << 16);
        *(uint32_t*)(sm3 + O_AL + rt_l*272 + dd*2) = (p0 >> 16) | (p1 & 0xffff0000u);
    }
    __syncthreads();

    const int g = lane >> 3, r = lane & 7;
    const int wm = (wid & 1) * 32;
    const int wn = (wid >> 1) * 32;
    uint32_t aoffH[2], aoffL[2];
    #pragma unroll
    for (int mi = 0; mi < 2; ++mi) {
        const uint32_t bse = (uint32_t)((wm + mi*16 + r + (g&1)*8) * 272 + ((g>>1)*8)*2);
        aoffH[mi] = sb + O_AH + bse;
        aoffL[mi] = sb + O_AL + bse;
    }
    const uint4* __restrict__ fw = g_wfrag + 5 * 4096 + lane;
    const int pbase = wn >> 4;

    float acc[2][4][4] = {};
    #pragma unroll
    for (int kc = 0; kc < 8; ++kc) {
        uint32_t AH[2][4], AL[2][4];
        #pragma unroll
        for (int mi = 0; mi < 2; ++mi) {
            ldm4(AH[mi], aoffH[mi] + kc*32);
            ldm4(AL[mi], aoffL[mi] + kc*32);
        }
        #pragma unroll
        for (int p4 = 0; p4 < 2; ++p4) {
            const int fidx = ((kc*8 + pbase + p4) * 2) * 32;
            const uint4 bh = fw[fidx];
            const uint4 bl = fw[fidx + 32];
            #pragma unroll
            for (int ns = 0; ns < 2; ++ns) {
                const int ni = p4*2 + ns;
                const uint32_t h0 = ns ? bh.z : bh.x, h1 = ns ? bh.w : bh.y;
                const uint32_t l0 = ns ? bl.z : bl.x, l1 = ns ? bl.w : bl.y;
                #pragma unroll
                for (int mi = 0; mi < 2; ++mi) {
                    mma_bf16(acc[mi][ni], AH[mi], h0, h1);
                    mma_bf16(acc[mi][ni], AH[mi], l0, l1);
                    mma_bf16(acc[mi][ni], AL[mi], h0, h1);
                }
            }
        }
    }
    __syncthreads();

    float* stagef = mixbuf;   // reuse as [64][132]
    #pragma unroll
    for (int mi = 0; mi < 2; ++mi)
        #pragma unroll
        for (int ni = 0; ni < 4; ++ni) {
            const int m0 = wm + mi*16 + (lane >> 2);
            const int n  = wn + ni*8 + (lane & 3)*2;
            const float b0 = __ldg(bout + n), b1 = __ldg(bout + n + 1);
            stagef[ m0   *132 + n    ] = acc[mi][ni][0] + b0;
            stagef[ m0   *132 + n + 1] = acc[mi][ni][1] + b1;
            stagef[(m0+8)*132 + n    ] = acc[mi][ni][2] + b0;
            stagef[(m0+8)*132 + n + 1] = acc[mi][ni][3] + b1;
        }
    __syncthreads();

    #pragma unroll
    for (int it = 0; it < 8; ++it) {
        const int idx = it * 256 + tid;
        const int row = idx >> 5, c4 = idx & 31;
        float4 v;
        v.x = stagef[row*132 + c4*4 + 0];
        v.y = stagef[row*132 + c4*4 + 1];
        v.z = stagef[row*132 + c4*4 + 2];
        v.w = stagef[row*132 + c4*4 + 3];
        *reinterpret_cast<float4*>(
            out + ((size_t)(ibase + row)*512 + j)*DD + c4*4) = v;
    }
}

// ---------------------------------------------------------------------------
extern "C" void kernel_launch(void* const* d_in, const int* in_sizes, int n_in,
                              void* d_out, int out_size)
{
    const float* x    = (const float*)d_in[0];
    const float* mskp = (const float*)d_in[1];
    const float* nsc  = (const float*)d_in[2];
    const float* nbi  = (const float*)d_in[3];
    const float* Wl   = (const float*)d_in[4];
    const float* bl   = (const float*)d_in[5];
    const float* Wr   = (const float*)d_in[6];
    const float* br   = (const float*)d_in[7];
    const float* Wlg  = (const float*)d_in[8];
    const float* blg  = (const float*)d_in[9];
    const float* Wrg  = (const float*)d_in[10];
    const float* brg  = (const float*)d_in[11];
    const float* Wog  = (const float*)d_in[12];
    const float* bog  = (const float*)d_in[13];
    const float* gs   = (const float*)d_in[14];
    const float* gb   = (const float*)d_in[15];
    const float* Wout = (const float*)d_in[16];
    const float* bout = (const float*)d_in[17];
    float* out = (float*)d_out;

    cudaFuncSetAttribute(einsum_mma_kernel,
                         cudaFuncAttributeMaxDynamicSharedMemorySize, E3_SMEM);
    cudaFuncSetAttribute(ln_proj_mma_kernel,
                         cudaFuncAttributeMaxDynamicSharedMemorySize, K1_SMEM);
    cudaFuncSetAttribute(out_mma_kernel,
                         cudaFuncAttributeMaxDynamicSharedMemorySize, O_SMEM);

    wprep_kernel<<<6, 256>>>(Wlg, Wl, Wrg, Wr, Wog, Wout);
    ln_proj_mma_kernel<<<4096, 256, K1_SMEM>>>(x, mskp, nsc, nbi,
                                               bl, br, blg, brg, bog);
    einsum_mma_kernel<<<dim3(32, 128), 256, E3_SMEM>>>();
    out_mma_kernel<<<4096, 256, O_SMEM>>>(gs, gb, bout, out);
}

// round 10
// speedup vs baseline: 1.1875x; 1.0134x over previous
#include <cuda_runtime.h>
#include <cuda_bf16.h>
#include <cuda_fp16.h>
#include <math.h>
#include <stdint.h>

// Problem constants
#define NTOK 512
#define DD   128
#define NN   (NTOK*NTOK)

// Scratch (static __device__ arrays — no allocation allowed)
//   g_ab[arr][c][row*512+k] bf16, arr: 0=left-hi 1=left-lo 2=right-hi 3=right-lo
//   g_og  [c][j*512+i] fp16 sigmoid(out-gate)
//   g_mix [d][j*512+i] einsum result f32
//   g_wfrag[w][kc][p][spl][lane] uint4 — B-fragment-ready weights
__device__ __nv_bfloat16 g_ab[134217728];
__device__ __half        g_og [33554432];
__device__ float         g_mix[33554432];
__device__ __align__(16) uint4 g_wfrag[6 * 4096];

#define ARRSZ (128*NN)

// ---------------------------------------------------------------------------
// helpers
// ---------------------------------------------------------------------------
__device__ __forceinline__ uint32_t smem_u32(const void* p) {
    uint32_t a;
    asm("{ .reg .u64 t; cvta.to.shared.u64 t, %1; cvt.u32.u64 %0, t; }"
        : "=r"(a) : "l"(p));
    return a;
}

__device__ __forceinline__ void ldm4(uint32_t r[4], uint32_t addr) {
    asm volatile("ldmatrix.sync.aligned.m8n8.x4.shared.b16 {%0,%1,%2,%3}, [%4];"
                 : "=r"(r[0]), "=r"(r[1]), "=r"(r[2]), "=r"(r[3]) : "r"(addr));
}

__device__ __forceinline__ void mma_bf16(float acc[4], const uint32_t a[4],
                                         uint32_t b0, uint32_t b1) {
    asm volatile(
        "mma.sync.aligned.m16n8k16.row.col.f32.bf16.bf16.f32 "
        "{%0,%1,%2,%3}, {%4,%5,%6,%7}, {%8,%9}, {%0,%1,%2,%3};"
        : "+f"(acc[0]), "+f"(acc[1]), "+f"(acc[2]), "+f"(acc[3])
        : "r"(a[0]), "r"(a[1]), "r"(a[2]), "r"(a[3]), "r"(b0), "r"(b1));
}

#define CPASYNC16(dst, src) \
    asm volatile("cp.async.cg.shared.global [%0], [%1], 16;" \
                 :: "r"(dst), "l"(src) : "memory")
#define CPCOMMIT() asm volatile("cp.async.commit_group;" ::: "memory")
#define CPWAIT1()  asm volatile("cp.async.wait_group 1;" ::: "memory")
#define CPWAIT0()  asm volatile("cp.async.wait_group 0;" ::: "memory")

__device__ __forceinline__ float sigmoidf_(float z) {
    return 1.f / (1.f + expf(-z));
}

__device__ __forceinline__ uint32_t split_pack(float v) {
    __nv_bfloat16 h = __float2bfloat16(v);
    __nv_bfloat16 l = __float2bfloat16(v - __bfloat162float(h));
    uint16_t hu = *(uint16_t*)&h, lu = *(uint16_t*)&l;
    return (uint32_t)hu | ((uint32_t)lu << 16);
}

// ---------------------------------------------------------------------------
// Kernel 0: weights -> B-fragment layout (hi/lo), register-ready for mma.sync.
// ---------------------------------------------------------------------------
__global__ void wprep_kernel(const float* __restrict__ W0, const float* __restrict__ W1,
                             const float* __restrict__ W2, const float* __restrict__ W3,
                             const float* __restrict__ W4, const float* __restrict__ W5)
{
    const float* W = (blockIdx.x == 0) ? W0 : (blockIdx.x == 1) ? W1 :
                     (blockIdx.x == 2) ? W2 : (blockIdx.x == 3) ? W3 :
                     (blockIdx.x == 4) ? W4 : W5;
    uint4* dst = g_wfrag + blockIdx.x * 4096;
    for (int idx = threadIdx.x; idx < 4096; idx += 256) {
        const int lane = idx & 31;
        const int spl  = (idx >> 5) & 1;
        const int p    = (idx >> 6) & 7;
        const int kc   = idx >> 9;
        const int nf = p * 16 + (lane >> 2);
        const int k0 = kc * 16 + 2 * (lane & 3);
        uint16_t e[8];
        #pragma unroll
        for (int q = 0; q < 8; ++q) {
            const int k = k0 + (q & 1) + ((q >> 1) & 1) * 8;
            const int n = nf + (q >> 2) * 8;
            const float v = W[k * 128 + n];
            __nv_bfloat16 h = __float2bfloat16(v);
            __nv_bfloat16 l = __float2bfloat16(v - __bfloat162float(h));
            e[q] = spl ? *(uint16_t*)&l : *(uint16_t*)&h;
        }
        uint4 o;
        o.x = (uint32_t)e[0] | ((uint32_t)e[1] << 16);
        o.y = (uint32_t)e[2] | ((uint32_t)e[3] << 16);
        o.z = (uint32_t)e[4] | ((uint32_t)e[5] << 16);
        o.w = (uint32_t)e[6] | ((uint32_t)e[7] << 16);
        dst[idx] = o;
    }
}

// ---------------------------------------------------------------------------
// Kernel 1: LayerNorm + 5 projections (fused value+gate). 64-row blocks,
// 8 warps 2m x 4n, 2 CTAs/SM.
// ---------------------------------------------------------------------------
#define K1_AH   0
#define K1_AL   17408
#define K1_ST   34816
#define K1_MS   67840
#define K1_SMEM 68096

template<bool PAIR>
__device__ __forceinline__ void k1_pass2(
    char* sm1, uint32_t sb, int wv, int wg,
    const float* __restrict__ bv, const float* __restrict__ bg,
    int tid, int lane, int wm, int wn,
    __nv_bfloat16* dst_h, __nv_bfloat16* dst_l, __half* dst_og, size_t gbase)
{
    const int g = lane >> 3, r = lane & 7;
    uint32_t aoffH[2], aoffL[2];
    #pragma unroll
    for (int mi = 0; mi < 2; ++mi) {
        const uint32_t base = (uint32_t)((wm + mi*16 + r + (g&1)*8) * 272 + ((g>>1)*8)*2);
        aoffH[mi] = sb + K1_AH + base;
        aoffL[mi] = sb + K1_AL + base;
    }
    const uint4* __restrict__ fv = g_wfrag + wv * 4096 + lane;
    const uint4* __restrict__ fg = g_wfrag + wg * 4096 + lane;
    const int pbase = wn >> 4;

    float accV[2][4][4] = {};
    float accG[PAIR ? 2 : 1][4][4] = {};

    #pragma unroll
    for (int kc = 0; kc < 8; ++kc) {
        uint32_t AH[2][4], AL[2][4];
        #pragma unroll
        for (int mi = 0; mi < 2; ++mi) {
            ldm4(AH[mi], aoffH[mi] + kc*32);
            ldm4(AL[mi], aoffL[mi] + kc*32);
        }
        #pragma unroll
        for (int p4 = 0; p4 < 2; ++p4) {
            const int fidx = ((kc*8 + pbase + p4) * 2) * 32;
            const uint4 bvh = fv[fidx];
            const uint4 bvl = fv[fidx + 32];
            uint4 bgh, bgl;
            if (PAIR) { bgh = fg[fidx]; bgl = fg[fidx + 32]; }
            #pragma unroll
            for (int ns = 0; ns < 2; ++ns) {
                const int ni = p4*2 + ns;
                const uint32_t v0 = ns ? bvh.z : bvh.x, v1 = ns ? bvh.w : bvh.y;
                const uint32_t l0 = ns ? bvl.z : bvl.x, l1 = ns ? bvl.w : bvl.y;
                #pragma unroll
                for (int mi = 0; mi < 2; ++mi) {
                    mma_bf16(accV[mi][ni], AH[mi], v0, v1);
                    mma_bf16(accV[mi][ni], AH[mi], l0, l1);
                    mma_bf16(accV[mi][ni], AL[mi], v0, v1);
                }
                if (PAIR) {
                    const uint32_t g0 = ns ? bgh.z : bgh.x, g1 = ns ? bgh.w : bgh.y;
                    const uint32_t m0 = ns ? bgl.z : bgl.x, m1 = ns ? bgl.w : bgl.y;
                    #pragma unroll
                    for (int mi = 0; mi < 2; ++mi) {
                        mma_bf16(accG[mi][ni], AH[mi], g0, g1);
                        mma_bf16(accG[mi][ni], AH[mi], m0, m1);
                        mma_bf16(accG[mi][ni], AL[mi], g0, g1);
                    }
                }
            }
        }
    }

    float*    stagef = (float*)(sm1 + K1_ST);
    uint32_t* stageu = (uint32_t*)(sm1 + K1_ST);
    const float* mask_s = (const float*)(sm1 + K1_MS);

    #pragma unroll
    for (int mi = 0; mi < 2; ++mi)
        #pragma unroll
        for (int ni = 0; ni < 4; ++ni) {
            const int m0 = wm + mi*16 + (lane >> 2);
            const int n  = wn + ni*8 + (lane & 3)*2;
            const float b0 = __ldg(bv + n), b1 = __ldg(bv + n + 1);
            float* a = accV[mi][ni];
            if (PAIR) {
                const float c0 = __ldg(bg + n), c1 = __ldg(bg + n + 1);
                const float* gacc = accG[mi][ni];
                const float mk0 = mask_s[m0], mk1 = mask_s[m0 + 8];
                stageu[ m0   *129 + n    ] = split_pack((a[0]+b0)*mk0*sigmoidf_(gacc[0]+c0));
                stageu[ m0   *129 + n + 1] = split_pack((a[1]+b1)*mk0*sigmoidf_(gacc[1]+c1));
                stageu[(m0+8)*129 + n    ] = split_pack((a[2]+b0)*mk1*sigmoidf_(gacc[2]+c0));
                stageu[(m0+8)*129 + n + 1] = split_pack((a[3]+b1)*mk1*sigmoidf_(gacc[3]+c1));
            } else {
                stagef[ m0   *129 + n    ] = sigmoidf_(a[0] + b0);
                stagef[ m0   *129 + n + 1] = sigmoidf_(a[1] + b1);
                stagef[(m0+8)*129 + n    ] = sigmoidf_(a[2] + b0);
                stagef[(m0+8)*129 + n + 1] = sigmoidf_(a[3] + b1);
            }
        }
    __syncthreads();

    if (PAIR) {
        #pragma unroll
        for (int it = 0; it < 16; ++it) {
            const int idx = it * 256 + tid;
            const int c  = idx >> 5;
            const int rp = (idx & 31) * 2;
            const uint32_t u0 = stageu[ rp      * 129 + c];
            const uint32_t u1 = stageu[(rp + 1) * 129 + c];
            const size_t addr = (size_t)c * NN + gbase + rp;
            *(uint32_t*)(dst_h + addr) = (u0 & 0xffffu) | (u1 << 16);
            *(uint32_t*)(dst_l + addr) = (u0 >> 16) | (u1 & 0xffff0000u);
        }
    } else {
        #pragma unroll
        for (int it = 0; it < 16; ++it) {
            const int idx = it * 256 + tid;
            const int c  = idx >> 5;
            const int rp = (idx & 31) * 2;
            __half2 h2 = __floats2half2_rn(stagef[rp*129 + c], stagef[(rp+1)*129 + c]);
            *(__half2*)(dst_og + (size_t)c * NN + gbase + rp) = h2;
        }
    }
    __syncthreads();
}

__global__ __launch_bounds__(256, 2) void ln_proj_mma_kernel(
    const float* __restrict__ x,   const float* __restrict__ msk,
    const float* __restrict__ nsc, const float* __restrict__ nbi,
    const float* __restrict__ bl,  const float* __restrict__ br,
    const float* __restrict__ blg, const float* __restrict__ brg,
    const float* __restrict__ bog)
{
    extern __shared__ __align__(16) char sm1[];
    const int tid  = threadIdx.x;
    const int lane = tid & 31;
    const int wid  = tid >> 5;
    const int n2   = blockIdx.x & 511;
    const int n1b  = (blockIdx.x >> 9) << 6;
    const uint32_t sb = smem_u32(sm1);

    {
        const int row = tid >> 2, sub = tid & 3;
        const float4* xr = reinterpret_cast<const float4*>(
                               x + ((size_t)(n1b + row) * 512 + n2) * DD) + sub * 8;
        float4 v[8];
        float s = 0.f, ss = 0.f;
        #pragma unroll
        for (int q = 0; q < 8; ++q) {
            v[q] = xr[q];
            s  += v[q].x + v[q].y + v[q].z + v[q].w;
            ss += v[q].x*v[q].x + v[q].y*v[q].y + v[q].z*v[q].z + v[q].w*v[q].w;
        }
        s  += __shfl_xor_sync(0xffffffffu, s, 1);
        ss += __shfl_xor_sync(0xffffffffu, ss, 1);
        s  += __shfl_xor_sync(0xffffffffu, s, 2);
        ss += __shfl_xor_sync(0xffffffffu, ss, 2);
        const float mu   = s * (1.f/128.f);
        const float var  = ss * (1.f/128.f) - mu*mu;
        const float rstd = rsqrtf(var + 1e-6f);
        #pragma unroll
        for (int q = 0; q < 8; ++q) {
            const int d0 = sub*32 + q*4;
            float a0 = (v[q].x - mu)*rstd*__ldg(&nsc[d0+0]) + __ldg(&nbi[d0+0]);
            float a1 = (v[q].y - mu)*rstd*__ldg(&nsc[d0+1]) + __ldg(&nbi[d0+1]);
            float a2 = (v[q].z - mu)*rstd*__ldg(&nsc[d0+2]) + __ldg(&nbi[d0+2]);
            float a3 = (v[q].w - mu)*rstd*__ldg(&nsc[d0+3]) + __ldg(&nbi[d0+3]);
            uint32_t p0 = split_pack(a0), p1 = split_pack(a1);
            uint32_t p2 = split_pack(a2), p3 = split_pack(a3);
            uint2 hw, lw;
            hw.x = (p0 & 0xffffu) | (p1 << 16);
            hw.y = (p2 & 0xffffu) | (p3 << 16);
            lw.x = (p0 >> 16) | (p1 & 0xffff0000u);
            lw.y = (p2 >> 16) | (p3 & 0xffff0000u);
            *(uint2*)(sm1 + K1_AH + row*272 + d0*2) = hw;
            *(uint2*)(sm1 + K1_AL + row*272 + d0*2) = lw;
        }
        if (sub == 0)
            ((float*)(sm1 + K1_MS))[row] = msk[n1b + row] * msk[n2];
    }
    __syncthreads();

    const int wm = (wid & 1) * 32;
    const int wn = (wid >> 1) * 32;
    const size_t gbase = (size_t)n2 * 512 + n1b;

    k1_pass2<true >(sm1, sb, 1, 0, bl,  blg, tid, lane, wm, wn,
                    g_ab, g_ab + ARRSZ, 0, gbase);
    k1_pass2<true >(sm1, sb, 3, 2, br,  brg, tid, lane, wm, wn,
                    g_ab + 2*(size_t)ARRSZ, g_ab + 3*(size_t)ARRSZ, 0, gbase);
    k1_pass2<false>(sm1, sb, 4, 4, bog, bog, tid, lane, wm, wn, 0, 0, g_og, gbase);
}

// ---------------------------------------------------------------------------
// Kernel 2: einsum via mma.sync bf16 (3-MMA split). 128x64 tiles,
// cp.async 3-stage ring, ONE sync per K-iteration, 2 CTAs/SM.
// ---------------------------------------------------------------------------
#define E3_STAGE 30720
#define E3_SMEM  92160

__global__ __launch_bounds__(256, 2) void einsum_mma_kernel()
{
    extern __shared__ __align__(16) char esm[];
    const int tid  = threadIdx.x;
    const int lane = tid & 31;
    const int wid  = tid >> 5;
    const int d    = blockIdx.y;
    const int i0   = (blockIdx.x & 3) * 128;
    const int j0   = (blockIdx.x >> 2) * 64;
    const uint32_t sbm = smem_u32(esm);

    const __nv_bfloat16* __restrict__ base = g_ab + (size_t)d * NN;

    uint32_t goff[6], soff[6];
    #pragma unroll
    for (int it = 0; it < 6; ++it) {
        int arr, rem;
        if (it < 4) { arr = it >> 1; rem = (it & 1) * 256 + tid; }
        else        { arr = it - 2;  rem = tid; }
        const int row = rem >> 2, seg = rem & 3;
        const int r0 = (arr < 2) ? i0 : j0;
        const uint32_t ab = (arr == 0) ? 0u : (arr == 1) ? 10240u :
                            (arr == 2) ? 20480u : 25600u;
        goff[it] = (uint32_t)(arr * ARRSZ) + (uint32_t)((r0 + row)*512 + seg*8);
        soff[it] = ab + (uint32_t)(row*80 + seg*16);
    }

    const int g = lane >> 3, r = lane & 7;
    const int wm = (wid & 3) * 32;
    const int wn = (wid >> 2) * 32;
    uint32_t aoff[2][2], boff[2][2];
    #pragma unroll
    for (int mi = 0; mi < 2; ++mi) {
        const uint32_t bse = (uint32_t)((wm + mi*16 + r + (g&1)*8)*80 + ((g>>1)*8)*2);
        aoff[0][mi] = sbm + bse;
        aoff[1][mi] = sbm + 10240 + bse;
    }
    #pragma unroll
    for (int p = 0; p < 2; ++p) {
        const uint32_t bse = (uint32_t)((wn + p*16 + r + (g>>1)*8)*80 + ((g&1)*8)*2);
        boff[0][p] = sbm + 20480 + bse;
        boff[1][p] = sbm + 25600 + bse;
    }

    float acc[2][4][4] = {};

    #pragma unroll
    for (int it = 0; it < 6; ++it)
        CPASYNC16(sbm + soff[it], base + goff[it]);
    CPCOMMIT();
    #pragma unroll
    for (int it = 0; it < 6; ++it)
        CPASYNC16(sbm + E3_STAGE + soff[it], base + goff[it] + 32);
    CPCOMMIT();

    #pragma unroll 1
    for (int kc = 0; kc < 16; ++kc) {
        if (kc < 15) { CPWAIT1(); } else { CPWAIT0(); }
        __syncthreads();

        if (kc < 14) {
            const uint32_t nstg = (uint32_t)((kc + 2) % 3) * E3_STAGE;
            const int kb = (kc + 2) * 32;
            #pragma unroll
            for (int it = 0; it < 6; ++it)
                CPASYNC16(sbm + nstg + soff[it], base + goff[it] + kb);
            CPCOMMIT();
        }

        const uint32_t stg = (uint32_t)(kc % 3) * E3_STAGE;
        #pragma unroll
        for (int ks2 = 0; ks2 < 2; ++ks2) {
            const uint32_t off = stg + (uint32_t)ks2 * 32;
            uint32_t AH[2][4], AL[2][4], BH[2][4], BL[2][4];
            #pragma unroll
            for (int mi = 0; mi < 2; ++mi) {
                ldm4(AH[mi], aoff[0][mi] + off);
                ldm4(AL[mi], aoff[1][mi] + off);
            }
            #pragma unroll
            for (int p = 0; p < 2; ++p) {
                ldm4(BH[p], boff[0][p] + off);
                ldm4(BL[p], boff[1][p] + off);
            }
            #pragma unroll
            for (int mi = 0; mi < 2; ++mi)
                #pragma unroll
                for (int ni = 0; ni < 4; ++ni) {
                    const int p = ni >> 1, h = (ni & 1) * 2;
                    mma_bf16(acc[mi][ni], AH[mi], BH[p][h], BH[p][h+1]);
                    mma_bf16(acc[mi][ni], AH[mi], BL[p][h], BL[p][h+1]);
                    mma_bf16(acc[mi][ni], AL[mi], BH[p][h], BH[p][h+1]);
                }
        }
    }
    __syncthreads();

    float* smT = (float*)esm;   // [64][132]
    #pragma unroll
    for (int mi = 0; mi < 2; ++mi)
        #pragma unroll
        for (int ni = 0; ni < 4; ++ni) {
            const int m = wm + mi*16 + (lane >> 2);
            const int j = wn + ni*8 + (lane & 3)*2;
            smT[(j  )*132 + m    ] = acc[mi][ni][0];
            smT[(j+1)*132 + m    ] = acc[mi][ni][1];
            smT[(j  )*132 + m + 8] = acc[mi][ni][2];
            smT[(j+1)*132 + m + 8] = acc[mi][ni][3];
        }
    __syncthreads();

    float* gm = g_mix + (size_t)d * NN;
    #pragma unroll
    for (int it = 0; it < 8; ++it) {
        const int idx = it*256 + tid;
        const int j = idx >> 5, c4 = idx & 31;
        float4 o;
        o.x = smT[j*132 + c4*4 + 0];
        o.y = smT[j*132 + c4*4 + 1];
        o.z = smT[j*132 + c4*4 + 2];
        o.w = smT[j*132 + c4*4 + 3];
        *reinterpret_cast<float4*>(gm + (size_t)(j0 + j)*512 + i0 + c4*4) = o;
    }
}

// ---------------------------------------------------------------------------
// Kernel 3: out-LN (over d) * out_gate, then @ W_out + b_out — MMA version.
// No smem mix buffer: g_mix read twice (2nd hits L2). smem 36.9KB -> 4 CTAs/SM.
// ---------------------------------------------------------------------------
#define O_AH    0
#define O_AL    17408
#define O_RED   34816
#define O_SMEM  36864

__global__ __launch_bounds__(256, 4) void out_mma_kernel(
    const float* __restrict__ gs, const float* __restrict__ gb,
    const float* __restrict__ bout, float* __restrict__ out)
{
    extern __shared__ __align__(16) char sm3[];
    const int tid  = threadIdx.x;
    const int lane = tid & 31;
    const int wid  = tid >> 5;
    const int rt0  = blockIdx.x * 64;
    const int j    = rt0 >> 9;
    const int ibase = rt0 & 511;
    const uint32_t sb = smem_u32(sm3);

    float* red = (float*)(sm3 + O_RED);     // [2][4][64]

    const int rt_l = tid & 63;
    const int qtr  = tid >> 6;
    const int d0   = qtr * 32;

    // ---- pass 1: LN stats over d (coalesced g_mix reads) ----
    float s = 0.f, q = 0.f;
    #pragma unroll 8
    for (int dd = d0; dd < d0 + 32; ++dd) {
        float v = g_mix[(size_t)dd*NN + rt0 + rt_l];
        s += v; q += v*v;
    }
    red[qtr*64 + rt_l]       = s;
    red[256 + qtr*64 + rt_l] = q;
    __syncthreads();
    const float S = red[rt_l] + red[64 + rt_l] + red[128 + rt_l] + red[192 + rt_l];
    const float Q = red[256 + rt_l] + red[320 + rt_l] + red[384 + rt_l] + red[448 + rt_l];
    const float mu   = S * (1.f/128.f);
    const float rstd = rsqrtf(Q * (1.f/128.f) - mu*mu + 1e-6f);

    // ---- pass 2: re-read g_mix (L2 hot) + g_og, gate & split into A ----
    #pragma unroll 4
    for (int dd = d0; dd < d0 + 32; dd += 2) {
        float v0 = g_mix[(size_t) dd     *NN + rt0 + rt_l];
        float v1 = g_mix[(size_t)(dd + 1)*NN + rt0 + rt_l];
        float o0 = __half2float(g_og[(size_t) dd     *NN + rt0 + rt_l]);
        float o1 = __half2float(g_og[(size_t)(dd + 1)*NN + rt0 + rt_l]);
        float g0 = ((v0 - mu)*rstd*__ldg(gs+dd)   + __ldg(gb+dd))   * o0;
        float g1 = ((v1 - mu)*rstd*__ldg(gs+dd+1) + __ldg(gb+dd+1)) * o1;
        uint32_t p0 = split_pack(g0), p1 = split_pack(g1);
        *(uint32_t*)(sm3 + O_AH + rt_l*272 + dd*2) = (p0 & 0xffffu) | (p1 << 16);
        *(uint32_t*)(sm3 + O_AL + rt_l*272 + dd*2) = (p0 >> 16) | (p1 & 0xffff0000u);
    }
    __syncthreads();

    // ---- MMA: [64 rt] x [128 c] x [128 d], Wout fragments via LDG ----
    const int g = lane >> 3, r = lane & 7;
    const int wm = (wid & 1) * 32;
    const int wn = (wid >> 1) * 32;
    uint32_t aoffH[2], aoffL[2];
    #pragma unroll
    for (int mi = 0; mi < 2; ++mi) {
        const uint32_t bse = (uint32_t)((wm + mi*16 + r + (g&1)*8) * 272 + ((g>>1)*8)*2);
        aoffH[mi] = sb + O_AH + bse;
        aoffL[mi] = sb + O_AL + bse;
    }
    const uint4* __restrict__ fw = g_wfrag + 5 * 4096 + lane;
    const int pbase = wn >> 4;

    float acc[2][4][4] = {};
    #pragma unroll
    for (int kc = 0; kc < 8; ++kc) {
        uint32_t AH[2][4], AL[2][4];
        #pragma unroll
        for (int mi = 0; mi < 2; ++mi) {
            ldm4(AH[mi], aoffH[mi] + kc*32);
            ldm4(AL[mi], aoffL[mi] + kc*32);
        }
        #pragma unroll
        for (int p4 = 0; p4 < 2; ++p4) {
            const int fidx = ((kc*8 + pbase + p4) * 2) * 32;
            const uint4 bh = fw[fidx];
            const uint4 bl = fw[fidx + 32];
            #pragma unroll
            for (int ns = 0; ns < 2; ++ns) {
                const int ni = p4*2 + ns;
                const uint32_t h0 = ns ? bh.z : bh.x, h1 = ns ? bh.w : bh.y;
                const uint32_t l0 = ns ? bl.z : bl.x, l1 = ns ? bl.w : bl.y;
                #pragma unroll
                for (int mi = 0; mi < 2; ++mi) {
                    mma_bf16(acc[mi][ni], AH[mi], h0, h1);
                    mma_bf16(acc[mi][ni], AH[mi], l0, l1);
                    mma_bf16(acc[mi][ni], AL[mi], h0, h1);
                }
            }
        }
    }
    __syncthreads();   // A reads done; reuse AH/AL region as out stage [64][132]

    float* stagef = (float*)(sm3 + O_AH);
    #pragma unroll
    for (int mi = 0; mi < 2; ++mi)
        #pragma unroll
        for (int ni = 0; ni < 4; ++ni) {
            const int m0 = wm + mi*16 + (lane >> 2);
            const int n  = wn + ni*8 + (lane & 3)*2;
            const float b0 = __ldg(bout + n), b1 = __ldg(bout + n + 1);
            stagef[ m0   *132 + n    ] = acc[mi][ni][0] + b0;
            stagef[ m0   *132 + n + 1] = acc[mi][ni][1] + b1;
            stagef[(m0+8)*132 + n    ] = acc[mi][ni][2] + b0;
            stagef[(m0+8)*132 + n + 1] = acc[mi][ni][3] + b1;
        }
    __syncthreads();

    #pragma unroll
    for (int it = 0; it < 8; ++it) {
        const int idx = it * 256 + tid;
        const int row = idx >> 5, c4 = idx & 31;
        float4 v;
        v.x = stagef[row*132 + c4*4 + 0];
        v.y = stagef[row*132 + c4*4 + 1];
        v.z = stagef[row*132 + c4*4 + 2];
        v.w = stagef[row*132 + c4*4 + 3];
        *reinterpret_cast<float4*>(
            out + ((size_t)(ibase + row)*512 + j)*DD + c4*4) = v;
    }
}

// ---------------------------------------------------------------------------
extern "C" void kernel_launch(void* const* d_in, const int* in_sizes, int n_in,
                              void* d_out, int out_size)
{
    const float* x    = (const float*)d_in[0];
    const float* mskp = (const float*)d_in[1];
    const float* nsc  = (const float*)d_in[2];
    const float* nbi  = (const float*)d_in[3];
    const float* Wl   = (const float*)d_in[4];
    const float* bl   = (const float*)d_in[5];
    const float* Wr   = (const float*)d_in[6];
    const float* br   = (const float*)d_in[7];
    const float* Wlg  = (const float*)d_in[8];
    const float* blg  = (const float*)d_in[9];
    const float* Wrg  = (const float*)d_in[10];
    const float* brg  = (const float*)d_in[11];
    const float* Wog  = (const float*)d_in[12];
    const float* bog  = (const float*)d_in[13];
    const float* gs   = (const float*)d_in[14];
    const float* gb   = (const float*)d_in[15];
    const float* Wout = (const float*)d_in[16];
    const float* bout = (const float*)d_in[17];
    float* out = (float*)d_out;

    cudaFuncSetAttribute(einsum_mma_kernel,
                         cudaFuncAttributeMaxDynamicSharedMemorySize, E3_SMEM);
    cudaFuncSetAttribute(ln_proj_mma_kernel,
                         cudaFuncAttributeMaxDynamicSharedMemorySize, K1_SMEM);
    cudaFuncSetAttribute(out_mma_kernel,
                         cudaFuncAttributeMaxDynamicSharedMemorySize, O_SMEM);

    wprep_kernel<<<6, 256>>>(Wlg, Wl, Wrg, Wr, Wog, Wout);
    ln_proj_mma_kernel<<<4096, 256, K1_SMEM>>>(x, mskp, nsc, nbi,
                                               bl, br, blg, brg, bog);
    einsum_mma_kernel<<<dim3(32, 128), 256, E3_SMEM>>>();
    out_mma_kernel<<<4096, 256, O_SMEM>>>(gs, gb, bout, out);
}

// round 11
// speedup vs baseline: 1.2090x; 1.0181x over previous
#include <cuda_runtime.h>
#include <cuda_bf16.h>
#include <cuda_fp16.h>
#include <math.h>
#include <stdint.h>

// Problem constants
#define NTOK 512
#define DD   128
#define NN   (NTOK*NTOK)

// Scratch (static __device__ arrays — no allocation allowed)
//   g_ab[arr][c][row*512+k] bf16, arr: 0=left-hi 1=left-lo 2=right-hi 3=right-lo
//   g_og  [c][j*512+i] fp16 sigmoid(out-gate)
//   g_mix [d][j*512+i] einsum result fp16
//   g_wfrag[w][kc][p][spl][lane] uint4 — B-fragment-ready weights
__device__ __nv_bfloat16 g_ab[134217728];
__device__ __half        g_og [33554432];
__device__ __half        g_mix[33554432];
__device__ __align__(16) uint4 g_wfrag[6 * 4096];

#define ARRSZ (128*NN)

// ---------------------------------------------------------------------------
// helpers
// ---------------------------------------------------------------------------
__device__ __forceinline__ uint32_t smem_u32(const void* p) {
    uint32_t a;
    asm("{ .reg .u64 t; cvta.to.shared.u64 t, %1; cvt.u32.u64 %0, t; }"
        : "=r"(a) : "l"(p));
    return a;
}

__device__ __forceinline__ void ldm4(uint32_t r[4], uint32_t addr) {
    asm volatile("ldmatrix.sync.aligned.m8n8.x4.shared.b16 {%0,%1,%2,%3}, [%4];"
                 : "=r"(r[0]), "=r"(r[1]), "=r"(r[2]), "=r"(r[3]) : "r"(addr));
}

__device__ __forceinline__ void mma_bf16(float acc[4], const uint32_t a[4],
                                         uint32_t b0, uint32_t b1) {
    asm volatile(
        "mma.sync.aligned.m16n8k16.row.col.f32.bf16.bf16.f32 "
        "{%0,%1,%2,%3}, {%4,%5,%6,%7}, {%8,%9}, {%0,%1,%2,%3};"
        : "+f"(acc[0]), "+f"(acc[1]), "+f"(acc[2]), "+f"(acc[3])
        : "r"(a[0]), "r"(a[1]), "r"(a[2]), "r"(a[3]), "r"(b0), "r"(b1));
}

#define CPASYNC16(dst, src) \
    asm volatile("cp.async.cg.shared.global [%0], [%1], 16;" \
                 :: "r"(dst), "l"(src) : "memory")
#define CPCOMMIT() asm volatile("cp.async.commit_group;" ::: "memory")
#define CPWAIT1()  asm volatile("cp.async.wait_group 1;" ::: "memory")
#define CPWAIT0()  asm volatile("cp.async.wait_group 0;" ::: "memory")

__device__ __forceinline__ float sigmoidf_(float z) {
    return 1.f / (1.f + expf(-z));
}

__device__ __forceinline__ uint32_t split_pack(float v) {
    __nv_bfloat16 h = __float2bfloat16(v);
    __nv_bfloat16 l = __float2bfloat16(v - __bfloat162float(h));
    uint16_t hu = *(uint16_t*)&h, lu = *(uint16_t*)&l;
    return (uint32_t)hu | ((uint32_t)lu << 16);
}

// ---------------------------------------------------------------------------
// Kernel 0: weights -> B-fragment layout (hi/lo), register-ready for mma.sync.
// ---------------------------------------------------------------------------
__global__ void wprep_kernel(const float* __restrict__ W0, const float* __restrict__ W1,
                             const float* __restrict__ W2, const float* __restrict__ W3,
                             const float* __restrict__ W4, const float* __restrict__ W5)
{
    const float* W = (blockIdx.x == 0) ? W0 : (blockIdx.x == 1) ? W1 :
                     (blockIdx.x == 2) ? W2 : (blockIdx.x == 3) ? W3 :
                     (blockIdx.x == 4) ? W4 : W5;
    uint4* dst = g_wfrag + blockIdx.x * 4096;
    for (int idx = threadIdx.x; idx < 4096; idx += 256) {
        const int lane = idx & 31;
        const int spl  = (idx >> 5) & 1;
        const int p    = (idx >> 6) & 7;
        const int kc   = idx >> 9;
        const int nf = p * 16 + (lane >> 2);
        const int k0 = kc * 16 + 2 * (lane & 3);
        uint16_t e[8];
        #pragma unroll
        for (int q = 0; q < 8; ++q) {
            const int k = k0 + (q & 1) + ((q >> 1) & 1) * 8;
            const int n = nf + (q >> 2) * 8;
            const float v = W[k * 128 + n];
            __nv_bfloat16 h = __float2bfloat16(v);
            __nv_bfloat16 l = __float2bfloat16(v - __bfloat162float(h));
            e[q] = spl ? *(uint16_t*)&l : *(uint16_t*)&h;
        }
        uint4 o;
        o.x = (uint32_t)e[0] | ((uint32_t)e[1] << 16);
        o.y = (uint32_t)e[2] | ((uint32_t)e[3] << 16);
        o.z = (uint32_t)e[4] | ((uint32_t)e[5] << 16);
        o.w = (uint32_t)e[6] | ((uint32_t)e[7] << 16);
        dst[idx] = o;
    }
}

// ---------------------------------------------------------------------------
// Kernel 1: LayerNorm + 5 projections (fused value+gate). 64-row blocks,
// 8 warps 2m x 4n, 2 CTAs/SM.
// ---------------------------------------------------------------------------
#define K1_AH   0
#define K1_AL   17408
#define K1_ST   34816
#define K1_MS   67840
#define K1_SMEM 68096

template<bool PAIR>
__device__ __forceinline__ void k1_pass2(
    char* sm1, uint32_t sb, int wv, int wg,
    const float* __restrict__ bv, const float* __restrict__ bg,
    int tid, int lane, int wm, int wn,
    __nv_bfloat16* dst_h, __nv_bfloat16* dst_l, __half* dst_og, size_t gbase)
{
    const int g = lane >> 3, r = lane & 7;
    uint32_t aoffH[2], aoffL[2];
    #pragma unroll
    for (int mi = 0; mi < 2; ++mi) {
        const uint32_t base = (uint32_t)((wm + mi*16 + r + (g&1)*8) * 272 + ((g>>1)*8)*2);
        aoffH[mi] = sb + K1_AH + base;
        aoffL[mi] = sb + K1_AL + base;
    }
    const uint4* __restrict__ fv = g_wfrag + wv * 4096 + lane;
    const uint4* __restrict__ fg = g_wfrag + wg * 4096 + lane;
    const int pbase = wn >> 4;

    float accV[2][4][4] = {};
    float accG[PAIR ? 2 : 1][4][4] = {};

    #pragma unroll
    for (int kc = 0; kc < 8; ++kc) {
        uint32_t AH[2][4], AL[2][4];
        #pragma unroll
        for (int mi = 0; mi < 2; ++mi) {
            ldm4(AH[mi], aoffH[mi] + kc*32);
            ldm4(AL[mi], aoffL[mi] + kc*32);
        }
        #pragma unroll
        for (int p4 = 0; p4 < 2; ++p4) {
            const int fidx = ((kc*8 + pbase + p4) * 2) * 32;
            const uint4 bvh = fv[fidx];
            const uint4 bvl = fv[fidx + 32];
            uint4 bgh, bgl;
            if (PAIR) { bgh = fg[fidx]; bgl = fg[fidx + 32]; }
            #pragma unroll
            for (int ns = 0; ns < 2; ++ns) {
                const int ni = p4*2 + ns;
                const uint32_t v0 = ns ? bvh.z : bvh.x, v1 = ns ? bvh.w : bvh.y;
                const uint32_t l0 = ns ? bvl.z : bvl.x, l1 = ns ? bvl.w : bvl.y;
                #pragma unroll
                for (int mi = 0; mi < 2; ++mi) {
                    mma_bf16(accV[mi][ni], AH[mi], v0, v1);
                    mma_bf16(accV[mi][ni], AH[mi], l0, l1);
                    mma_bf16(accV[mi][ni], AL[mi], v0, v1);
                }
                if (PAIR) {
                    const uint32_t g0 = ns ? bgh.z : bgh.x, g1 = ns ? bgh.w : bgh.y;
                    const uint32_t m0 = ns ? bgl.z : bgl.x, m1 = ns ? bgl.w : bgl.y;
                    #pragma unroll
                    for (int mi = 0; mi < 2; ++mi) {
                        mma_bf16(accG[mi][ni], AH[mi], g0, g1);
                        mma_bf16(accG[mi][ni], AH[mi], m0, m1);
                        mma_bf16(accG[mi][ni], AL[mi], g0, g1);
                    }
                }
            }
        }
    }

    float*    stagef = (float*)(sm1 + K1_ST);
    uint32_t* stageu = (uint32_t*)(sm1 + K1_ST);
    const float* mask_s = (const float*)(sm1 + K1_MS);

    #pragma unroll
    for (int mi = 0; mi < 2; ++mi)
        #pragma unroll
        for (int ni = 0; ni < 4; ++ni) {
            const int m0 = wm + mi*16 + (lane >> 2);
            const int n  = wn + ni*8 + (lane & 3)*2;
            const float b0 = __ldg(bv + n), b1 = __ldg(bv + n + 1);
            float* a = accV[mi][ni];
            if (PAIR) {
                const float c0 = __ldg(bg + n), c1 = __ldg(bg + n + 1);
                const float* gacc = accG[mi][ni];
                const float mk0 = mask_s[m0], mk1 = mask_s[m0 + 8];
                stageu[ m0   *129 + n    ] = split_pack((a[0]+b0)*mk0*sigmoidf_(gacc[0]+c0));
                stageu[ m0   *129 + n + 1] = split_pack((a[1]+b1)*mk0*sigmoidf_(gacc[1]+c1));
                stageu[(m0+8)*129 + n    ] = split_pack((a[2]+b0)*mk1*sigmoidf_(gacc[2]+c0));
                stageu[(m0+8)*129 + n + 1] = split_pack((a[3]+b1)*mk1*sigmoidf_(gacc[3]+c1));
            } else {
                stagef[ m0   *129 + n    ] = sigmoidf_(a[0] + b0);
                stagef[ m0   *129 + n + 1] = sigmoidf_(a[1] + b1);
                stagef[(m0+8)*129 + n    ] = sigmoidf_(a[2] + b0);
                stagef[(m0+8)*129 + n + 1] = sigmoidf_(a[3] + b1);
            }
        }
    __syncthreads();

    if (PAIR) {
        #pragma unroll
        for (int it = 0; it < 8; ++it) {
            const int idx = it * 256 + tid;        // 2048 = 128c x 16 row-quads
            const int c  = idx >> 4;
            const int rq = (idx & 15) * 4;
            const uint32_t u0 = stageu[(rq  )*129 + c];
            const uint32_t u1 = stageu[(rq+1)*129 + c];
            const uint32_t u2 = stageu[(rq+2)*129 + c];
            const uint32_t u3 = stageu[(rq+3)*129 + c];
            uint2 hh, ll;
            hh.x = (u0 & 0xffffu) | (u1 << 16);
            hh.y = (u2 & 0xffffu) | (u3 << 16);
            ll.x = (u0 >> 16) | (u1 & 0xffff0000u);
            ll.y = (u2 >> 16) | (u3 & 0xffff0000u);
            const size_t addr = (size_t)c * NN + gbase + rq;
            *(uint2*)(dst_h + addr) = hh;
            *(uint2*)(dst_l + addr) = ll;
        }
    } else {
        #pragma unroll
        for (int it = 0; it < 8; ++it) {
            const int idx = it * 256 + tid;        // 2048 = 128c x 16 row-quads
            const int c  = idx >> 4;
            const int rq = (idx & 15) * 4;
            __half2 a = __floats2half2_rn(stagef[(rq  )*129 + c], stagef[(rq+1)*129 + c]);
            __half2 b = __floats2half2_rn(stagef[(rq+2)*129 + c], stagef[(rq+3)*129 + c]);
            uint2 o;
            *(__half2*)&o.x = a;
            *(__half2*)&o.y = b;
            *(uint2*)(dst_og + (size_t)c * NN + gbase + rq) = o;
        }
    }
    __syncthreads();
}

__global__ __launch_bounds__(256, 2) void ln_proj_mma_kernel(
    const float* __restrict__ x,   const float* __restrict__ msk,
    const float* __restrict__ nsc, const float* __restrict__ nbi,
    const float* __restrict__ bl,  const float* __restrict__ br,
    const float* __restrict__ blg, const float* __restrict__ brg,
    const float* __restrict__ bog)
{
    extern __shared__ __align__(16) char sm1[];
    const int tid  = threadIdx.x;
    const int lane = tid & 31;
    const int wid  = tid >> 5;
    const int n2   = blockIdx.x & 511;
    const int n1b  = (blockIdx.x >> 9) << 6;
    const uint32_t sb = smem_u32(sm1);

    {
        const int row = tid >> 2, sub = tid & 3;
        const float4* xr = reinterpret_cast<const float4*>(
                               x + ((size_t)(n1b + row) * 512 + n2) * DD) + sub * 8;
        float4 v[8];
        float s = 0.f, ss = 0.f;
        #pragma unroll
        for (int q = 0; q < 8; ++q) {
            v[q] = xr[q];
            s  += v[q].x + v[q].y + v[q].z + v[q].w;
            ss += v[q].x*v[q].x + v[q].y*v[q].y + v[q].z*v[q].z + v[q].w*v[q].w;
        }
        s  += __shfl_xor_sync(0xffffffffu, s, 1);
        ss += __shfl_xor_sync(0xffffffffu, ss, 1);
        s  += __shfl_xor_sync(0xffffffffu, s, 2);
        ss += __shfl_xor_sync(0xffffffffu, ss, 2);
        const float mu   = s * (1.f/128.f);
        const float var  = ss * (1.f/128.f) - mu*mu;
        const float rstd = rsqrtf(var + 1e-6f);
        #pragma unroll
        for (int q = 0; q < 8; ++q) {
            const int d0 = sub*32 + q*4;
            float a0 = (v[q].x - mu)*rstd*__ldg(&nsc[d0+0]) + __ldg(&nbi[d0+0]);
            float a1 = (v[q].y - mu)*rstd*__ldg(&nsc[d0+1]) + __ldg(&nbi[d0+1]);
            float a2 = (v[q].z - mu)*rstd*__ldg(&nsc[d0+2]) + __ldg(&nbi[d0+2]);
            float a3 = (v[q].w - mu)*rstd*__ldg(&nsc[d0+3]) + __ldg(&nbi[d0+3]);
            uint32_t p0 = split_pack(a0), p1 = split_pack(a1);
            uint32_t p2 = split_pack(a2), p3 = split_pack(a3);
            uint2 hw, lw;
            hw.x = (p0 & 0xffffu) | (p1 << 16);
            hw.y = (p2 & 0xffffu) | (p3 << 16);
            lw.x = (p0 >> 16) | (p1 & 0xffff0000u);
            lw.y = (p2 >> 16) | (p3 & 0xffff0000u);
            *(uint2*)(sm1 + K1_AH + row*272 + d0*2) = hw;
            *(uint2*)(sm1 + K1_AL + row*272 + d0*2) = lw;
        }
        if (sub == 0)
            ((float*)(sm1 + K1_MS))[row] = msk[n1b + row] * msk[n2];
    }
    __syncthreads();

    const int wm = (wid & 1) * 32;
    const int wn = (wid >> 1) * 32;
    const size_t gbase = (size_t)n2 * 512 + n1b;

    k1_pass2<true >(sm1, sb, 1, 0, bl,  blg, tid, lane, wm, wn,
                    g_ab, g_ab + ARRSZ, 0, gbase);
    k1_pass2<true >(sm1, sb, 3, 2, br,  brg, tid, lane, wm, wn,
                    g_ab + 2*(size_t)ARRSZ, g_ab + 3*(size_t)ARRSZ, 0, gbase);
    k1_pass2<false>(sm1, sb, 4, 4, bog, bog, tid, lane, wm, wn, 0, 0, g_og, gbase);
}

// ---------------------------------------------------------------------------
// Kernel 2: einsum via mma.sync bf16 (3-MMA split). 128x64 tiles,
// cp.async 3-stage ring, ONE sync per K-iteration, 2 CTAs/SM.
// Epilogue stores fp16 g_mix.
// ---------------------------------------------------------------------------
#define E3_STAGE 30720
#define E3_SMEM  92160

__global__ __launch_bounds__(256, 2) void einsum_mma_kernel()
{
    extern __shared__ __align__(16) char esm[];
    const int tid  = threadIdx.x;
    const int lane = tid & 31;
    const int wid  = tid >> 5;
    const int d    = blockIdx.y;
    const int i0   = (blockIdx.x & 3) * 128;
    const int j0   = (blockIdx.x >> 2) * 64;
    const uint32_t sbm = smem_u32(esm);

    const __nv_bfloat16* __restrict__ base = g_ab + (size_t)d * NN;

    uint32_t goff[6], soff[6];
    #pragma unroll
    for (int it = 0; it < 6; ++it) {
        int arr, rem;
        if (it < 4) { arr = it >> 1; rem = (it & 1) * 256 + tid; }
        else        { arr = it - 2;  rem = tid; }
        const int row = rem >> 2, seg = rem & 3;
        const int r0 = (arr < 2) ? i0 : j0;
        const uint32_t ab = (arr == 0) ? 0u : (arr == 1) ? 10240u :
                            (arr == 2) ? 20480u : 25600u;
        goff[it] = (uint32_t)(arr * ARRSZ) + (uint32_t)((r0 + row)*512 + seg*8);
        soff[it] = ab + (uint32_t)(row*80 + seg*16);
    }

    const int g = lane >> 3, r = lane & 7;
    const int wm = (wid & 3) * 32;
    const int wn = (wid >> 2) * 32;
    uint32_t aoff[2][2], boff[2][2];
    #pragma unroll
    for (int mi = 0; mi < 2; ++mi) {
        const uint32_t bse = (uint32_t)((wm + mi*16 + r + (g&1)*8)*80 + ((g>>1)*8)*2);
        aoff[0][mi] = sbm + bse;
        aoff[1][mi] = sbm + 10240 + bse;
    }
    #pragma unroll
    for (int p = 0; p < 2; ++p) {
        const uint32_t bse = (uint32_t)((wn + p*16 + r + (g>>1)*8)*80 + ((g&1)*8)*2);
        boff[0][p] = sbm + 20480 + bse;
        boff[1][p] = sbm + 25600 + bse;
    }

    float acc[2][4][4] = {};

    #pragma unroll
    for (int it = 0; it < 6; ++it)
        CPASYNC16(sbm + soff[it], base + goff[it]);
    CPCOMMIT();
    #pragma unroll
    for (int it = 0; it < 6; ++it)
        CPASYNC16(sbm + E3_STAGE + soff[it], base + goff[it] + 32);
    CPCOMMIT();

    #pragma unroll 1
    for (int kc = 0; kc < 16; ++kc) {
        if (kc < 15) { CPWAIT1(); } else { CPWAIT0(); }
        __syncthreads();

        if (kc < 14) {
            const uint32_t nstg = (uint32_t)((kc + 2) % 3) * E3_STAGE;
            const int kb = (kc + 2) * 32;
            #pragma unroll
            for (int it = 0; it < 6; ++it)
                CPASYNC16(sbm + nstg + soff[it], base + goff[it] + kb);
            CPCOMMIT();
        }

        const uint32_t stg = (uint32_t)(kc % 3) * E3_STAGE;
        #pragma unroll
        for (int ks2 = 0; ks2 < 2; ++ks2) {
            const uint32_t off = stg + (uint32_t)ks2 * 32;
            uint32_t AH[2][4], AL[2][4], BH[2][4], BL[2][4];
            #pragma unroll
            for (int mi = 0; mi < 2; ++mi) {
                ldm4(AH[mi], aoff[0][mi] + off);
                ldm4(AL[mi], aoff[1][mi] + off);
            }
            #pragma unroll
            for (int p = 0; p < 2; ++p) {
                ldm4(BH[p], boff[0][p] + off);
                ldm4(BL[p], boff[1][p] + off);
            }
            #pragma unroll
            for (int mi = 0; mi < 2; ++mi)
                #pragma unroll
                for (int ni = 0; ni < 4; ++ni) {
                    const int p = ni >> 1, h = (ni & 1) * 2;
                    mma_bf16(acc[mi][ni], AH[mi], BH[p][h], BH[p][h+1]);
                    mma_bf16(acc[mi][ni], AH[mi], BL[p][h], BL[p][h+1]);
                    mma_bf16(acc[mi][ni], AL[mi], BH[p][h], BH[p][h+1]);
                }
        }
    }
    __syncthreads();

    float* smT = (float*)esm;   // [64][132]
    #pragma unroll
    for (int mi = 0; mi < 2; ++mi)
        #pragma unroll
        for (int ni = 0; ni < 4; ++ni) {
            const int m = wm + mi*16 + (lane >> 2);
            const int j = wn + ni*8 + (lane & 3)*2;
            smT[(j  )*132 + m    ] = acc[mi][ni][0];
            smT[(j+1)*132 + m    ] = acc[mi][ni][1];
            smT[(j  )*132 + m + 8] = acc[mi][ni][2];
            smT[(j+1)*132 + m + 8] = acc[mi][ni][3];
        }
    __syncthreads();

    __half* gm = g_mix + (size_t)d * NN;
    #pragma unroll
    for (int it = 0; it < 8; ++it) {
        const int idx = it*256 + tid;      // 64 rows x 32 quads
        const int j = idx >> 5, c4 = idx & 31;
        __half2 h0 = __floats2half2_rn(smT[j*132 + c4*4 + 0], smT[j*132 + c4*4 + 1]);
        __half2 h1 = __floats2half2_rn(smT[j*132 + c4*4 + 2], smT[j*132 + c4*4 + 3]);
        uint2 o;
        *(__half2*)&o.x = h0;
        *(__half2*)&o.y = h1;
        *(uint2*)(gm + (size_t)(j0 + j)*512 + i0 + c4*4) = o;
    }
}

// ---------------------------------------------------------------------------
// Kernel 3: out-LN (over d) * out_gate, then @ W_out + b_out — MMA version.
// fp16 g_mix read twice (2nd hits L2). smem 36.9KB -> 4 CTAs/SM.
// ---------------------------------------------------------------------------
#define O_AH    0
#define O_AL    17408
#define O_RED   34816
#define O_SMEM  36864

__global__ __launch_bounds__(256, 4) void out_mma_kernel(
    const float* __restrict__ gs, const float* __restrict__ gb,
    const float* __restrict__ bout, float* __restrict__ out)
{
    extern __shared__ __align__(16) char sm3[];
    const int tid  = threadIdx.x;
    const int lane = tid & 31;
    const int wid  = tid >> 5;
    const int rt0  = blockIdx.x * 64;
    const int j    = rt0 >> 9;
    const int ibase = rt0 & 511;
    const uint32_t sb = smem_u32(sm3);

    float* red = (float*)(sm3 + O_RED);     // [2][4][64]

    const int rt_l = tid & 63;
    const int qtr  = tid >> 6;
    const int d0   = qtr * 32;

    // ---- pass 1: LN stats over d ----
    float s = 0.f, q = 0.f;
    #pragma unroll 8
    for (int dd = d0; dd < d0 + 32; ++dd) {
        float v = __half2float(g_mix[(size_t)dd*NN + rt0 + rt_l]);
        s += v; q += v*v;
    }
    red[qtr*64 + rt_l]       = s;
    red[256 + qtr*64 + rt_l] = q;
    __syncthreads();
    const float S = red[rt_l] + red[64 + rt_l] + red[128 + rt_l] + red[192 + rt_l];
    const float Q = red[256 + rt_l] + red[320 + rt_l] + red[384 + rt_l] + red[448 + rt_l];
    const float mu   = S * (1.f/128.f);
    const float rstd = rsqrtf(Q * (1.f/128.f) - mu*mu + 1e-6f);

    // ---- pass 2: re-read g_mix (L2 hot) + g_og, gate & split into A ----
    #pragma unroll 4
    for (int dd = d0; dd < d0 + 32; dd += 2) {
        float v0 = __half2float(g_mix[(size_t) dd     *NN + rt0 + rt_l]);
        float v1 = __half2float(g_mix[(size_t)(dd + 1)*NN + rt0 + rt_l]);
        float o0 = __half2float(g_og[(size_t) dd     *NN + rt0 + rt_l]);
        float o1 = __half2float(g_og[(size_t)(dd + 1)*NN + rt0 + rt_l]);
        float g0 = ((v0 - mu)*rstd*__ldg(gs+dd)   + __ldg(gb+dd))   * o0;
        float g1 = ((v1 - mu)*rstd*__ldg(gs+dd+1) + __ldg(gb+dd+1)) * o1;
        uint32_t p0 = split_pack(g0), p1 = split_pack(g1);
        *(uint32_t*)(sm3 + O_AH + rt_l*272 + dd*2) = (p0 & 0xffffu) | (p1 << 16);
        *(uint32_t*)(sm3 + O_AL + rt_l*272 + dd*2) = (p0 >> 16) | (p1 & 0xffff0000u);
    }
    __syncthreads();

    // ---- MMA: [64 rt] x [128 c] x [128 d], Wout fragments via LDG ----
    const int g = lane >> 3, r = lane & 7;
    const int wm = (wid & 1) * 32;
    const int wn = (wid >> 1) * 32;
    uint32_t aoffH[2], aoffL[2];
    #pragma unroll
    for (int mi = 0; mi < 2; ++mi) {
        const uint32_t bse = (uint32_t)((wm + mi*16 + r + (g&1)*8) * 272 + ((g>>1)*8)*2);
        aoffH[mi] = sb + O_AH + bse;
        aoffL[mi] = sb + O_AL + bse;
    }
    const uint4* __restrict__ fw = g_wfrag + 5 * 4096 + lane;
    const int pbase = wn >> 4;

    float acc[2][4][4] = {};
    #pragma unroll
    for (int kc = 0; kc < 8; ++kc) {
        uint32_t AH[2][4], AL[2][4];
        #pragma unroll
        for (int mi = 0; mi < 2; ++mi) {
            ldm4(AH[mi], aoffH[mi] + kc*32);
            ldm4(AL[mi], aoffL[mi] + kc*32);
        }
        #pragma unroll
        for (int p4 = 0; p4 < 2; ++p4) {
            const int fidx = ((kc*8 + pbase + p4) * 2) * 32;
            const uint4 bh = fw[fidx];
            const uint4 bl = fw[fidx + 32];
            #pragma unroll
            for (int ns = 0; ns < 2; ++ns) {
                const int ni = p4*2 + ns;
                const uint32_t h0 = ns ? bh.z : bh.x, h1 = ns ? bh.w : bh.y;
                const uint32_t l0 = ns ? bl.z : bl.x, l1 = ns ? bl.w : bl.y;
                #pragma unroll
                for (int mi = 0; mi < 2; ++mi) {
                    mma_bf16(acc[mi][ni], AH[mi], h0, h1);
                    mma_bf16(acc[mi][ni], AH[mi], l0, l1);
                    mma_bf16(acc[mi][ni], AL[mi], h0, h1);
                }
            }
        }
    }
    __syncthreads();   // A reads done; reuse AH/AL region as out stage [64][132]

    float* stagef = (float*)(sm3 + O_AH);
    #pragma unroll
    for (int mi = 0; mi < 2; ++mi)
        #pragma unroll
        for (int ni = 0; ni < 4; ++ni) {
            const int m0 = wm + mi*16 + (lane >> 2);
            const int n  = wn + ni*8 + (lane & 3)*2;
            const float b0 = __ldg(bout + n), b1 = __ldg(bout + n + 1);
            stagef[ m0   *132 + n    ] = acc[mi][ni][0] + b0;
            stagef[ m0   *132 + n + 1] = acc[mi][ni][1] + b1;
            stagef[(m0+8)*132 + n    ] = acc[mi][ni][2] + b0;
            stagef[(m0+8)*132 + n + 1] = acc[mi][ni][3] + b1;
        }
    __syncthreads();

    #pragma unroll
    for (int it = 0; it < 8; ++it) {
        const int idx = it * 256 + tid;
        const int row = idx >> 5, c4 = idx & 31;
        float4 v;
        v.x = stagef[row*132 + c4*4 + 0];
        v.y = stagef[row*132 + c4*4 + 1];
        v.z = stagef[row*132 + c4*4 + 2];
        v.w = stagef[row*132 + c4*4 + 3];
        *reinterpret_cast<float4*>(
            out + ((size_t)(ibase + row)*512 + j)*DD + c4*4) = v;
    }
}

// ---------------------------------------------------------------------------
extern "C" void kernel_launch(void* const* d_in, const int* in_sizes, int n_in,
                              void* d_out, int out_size)
{
    const float* x    = (const float*)d_in[0];
    const float* mskp = (const float*)d_in[1];
    const float* nsc  = (const float*)d_in[2];
    const float* nbi  = (const float*)d_in[3];
    const float* Wl   = (const float*)d_in[4];
    const float* bl   = (const float*)d_in[5];
    const float* Wr   = (const float*)d_in[6];
    const float* br   = (const float*)d_in[7];
    const float* Wlg  = (const float*)d_in[8];
    const float* blg  = (const float*)d_in[9];
    const float* Wrg  = (const float*)d_in[10];
    const float* brg  = (const float*)d_in[11];
    const float* Wog  = (const float*)d_in[12];
    const float* bog  = (const float*)d_in[13];
    const float* gs   = (const float*)d_in[14];
    const float* gb   = (const float*)d_in[15];
    const float* Wout = (const float*)d_in[16];
    const float* bout = (const float*)d_in[17];
    float* out = (float*)d_out;

    cudaFuncSetAttribute(einsum_mma_kernel,
                         cudaFuncAttributeMaxDynamicSharedMemorySize, E3_SMEM);
    cudaFuncSetAttribute(ln_proj_mma_kernel,
                         cudaFuncAttributeMaxDynamicSharedMemorySize, K1_SMEM);
    cudaFuncSetAttribute(out_mma_kernel,
                         cudaFuncAttributeMaxDynamicSharedMemorySize, O_SMEM);

    wprep_kernel<<<6, 256>>>(Wlg, Wl, Wrg, Wr, Wog, Wout);
    ln_proj_mma_kernel<<<4096, 256, K1_SMEM>>>(x, mskp, nsc, nbi,
                                               bl, br, blg, brg, bog);
    einsum_mma_kernel<<<dim3(32, 128), 256, E3_SMEM>>>();
    out_mma_kernel<<<4096, 256, O_SMEM>>>(gs, gb, bout, out);
}

// round 12
// speedup vs baseline: 1.5016x; 1.2420x over previous
#include <cuda_runtime.h>
#include <cuda_bf16.h>
#include <cuda_fp16.h>
#include <math.h>
#include <stdint.h>

// Problem constants
#define NTOK 512
#define DD   128
#define NN   (NTOK*NTOK)

// Scratch (static __device__ arrays — no allocation allowed)
//   g_ab[arr][c][row*512+k] fp16: arr 0=left-hi 1=left-lo 2=right(single)
//   g_og  [c][j*512+i] fp16 sigmoid(out-gate)
//   g_mix [d][j*512+i] einsum result fp16
//   g_wfrag[w][kc][p][lane] uint4 — fp16 B-fragment-ready weights (single)
__device__ __half        g_ab [100663296];
__device__ __half        g_og [33554432];
__device__ __half        g_mix[33554432];
__device__ __align__(16) uint4 g_wfrag[6 * 2048];

#define ARRSZ (128*NN)

// ---------------------------------------------------------------------------
// helpers
// ---------------------------------------------------------------------------
__device__ __forceinline__ uint32_t smem_u32(const void* p) {
    uint32_t a;
    asm("{ .reg .u64 t; cvta.to.shared.u64 t, %1; cvt.u32.u64 %0, t; }"
        : "=r"(a) : "l"(p));
    return a;
}

__device__ __forceinline__ void ldm4(uint32_t r[4], uint32_t addr) {
    asm volatile("ldmatrix.sync.aligned.m8n8.x4.shared.b16 {%0,%1,%2,%3}, [%4];"
                 : "=r"(r[0]), "=r"(r[1]), "=r"(r[2]), "=r"(r[3]) : "r"(addr));
}

__device__ __forceinline__ void mma_f16(float acc[4], const uint32_t a[4],
                                        uint32_t b0, uint32_t b1) {
    asm volatile(
        "mma.sync.aligned.m16n8k16.row.col.f32.f16.f16.f32 "
        "{%0,%1,%2,%3}, {%4,%5,%6,%7}, {%8,%9}, {%0,%1,%2,%3};"
        : "+f"(acc[0]), "+f"(acc[1]), "+f"(acc[2]), "+f"(acc[3])
        : "r"(a[0]), "r"(a[1]), "r"(a[2]), "r"(a[3]), "r"(b0), "r"(b1));
}

#define CPASYNC16(dst, src) \
    asm volatile("cp.async.cg.shared.global [%0], [%1], 16;" \
                 :: "r"(dst), "l"(src) : "memory")
#define CPCOMMIT() asm volatile("cp.async.commit_group;" ::: "memory")
#define CPWAIT1()  asm volatile("cp.async.wait_group 1;" ::: "memory")
#define CPWAIT0()  asm volatile("cp.async.wait_group 0;" ::: "memory")

__device__ __forceinline__ float sigmoidf_(float z) {
    return 1.f / (1.f + expf(-z));
}

// fp16 hi/lo split: low16 = hi fp16, high16 = lo fp16
__device__ __forceinline__ uint32_t split_pack(float v) {
    __half h = __float2half_rn(v);
    __half l = __float2half_rn(v - __half2float(h));
    uint16_t hu = *(uint16_t*)&h, lu = *(uint16_t*)&l;
    return (uint32_t)hu | ((uint32_t)lu << 16);
}

// ---------------------------------------------------------------------------
// Kernel 0: weights -> fp16 B-fragment layout, register-ready for mma.sync.
// 2048 uint4 per weight: [kc(8)][p(8)][lane(32)]
// ---------------------------------------------------------------------------
__global__ void wprep_kernel(const float* __restrict__ W0, const float* __restrict__ W1,
                             const float* __restrict__ W2, const float* __restrict__ W3,
                             const float* __restrict__ W4, const float* __restrict__ W5)
{
    const float* W = (blockIdx.x == 0) ? W0 : (blockIdx.x == 1) ? W1 :
                     (blockIdx.x == 2) ? W2 : (blockIdx.x == 3) ? W3 :
                     (blockIdx.x == 4) ? W4 : W5;
    uint4* dst = g_wfrag + blockIdx.x * 2048;
    for (int idx = threadIdx.x; idx < 2048; idx += 256) {
        const int lane = idx & 31;
        const int p    = (idx >> 5) & 7;
        const int kc   = idx >> 8;
        const int nf = p * 16 + (lane >> 2);
        const int k0 = kc * 16 + 2 * (lane & 3);
        uint16_t e[8];
        #pragma unroll
        for (int q = 0; q < 8; ++q) {
            const int k = k0 + (q & 1) + ((q >> 1) & 1) * 8;
            const int n = nf + (q >> 2) * 8;
            __half h = __float2half_rn(W[k * 128 + n]);
            e[q] = *(uint16_t*)&h;
        }
        uint4 o;
        o.x = (uint32_t)e[0] | ((uint32_t)e[1] << 16);
        o.y = (uint32_t)e[2] | ((uint32_t)e[3] << 16);
        o.z = (uint32_t)e[4] | ((uint32_t)e[5] << 16);
        o.w = (uint32_t)e[6] | ((uint32_t)e[7] << 16);
        dst[idx] = o;
    }
}

// ---------------------------------------------------------------------------
// Kernel 1: LayerNorm + 5 projections (fp16 2-split MMA, fused value+gate).
// 64-row blocks, 8 warps 2m x 4n, 2 CTAs/SM.
// MODE: 0 = left (store value hi/lo), 1 = right (store value single fp16),
//       2 = out-gate (store sigmoid single fp16)
// ---------------------------------------------------------------------------
#define K1_AH   0
#define K1_AL   17408
#define K1_ST   34816
#define K1_MS   67840
#define K1_SMEM 68096

template<int MODE>
__device__ __forceinline__ void k1_pass2(
    char* sm1, uint32_t sb, int wv, int wg,
    const float* __restrict__ bv, const float* __restrict__ bg,
    int tid, int lane, int wm, int wn,
    __half* dst_h, __half* dst_l, size_t gbase)
{
    constexpr bool PAIR = (MODE < 2);
    const int g = lane >> 3, r = lane & 7;
    uint32_t aoffH[2], aoffL[2];
    #pragma unroll
    for (int mi = 0; mi < 2; ++mi) {
        const uint32_t base = (uint32_t)((wm + mi*16 + r + (g&1)*8) * 272 + ((g>>1)*8)*2);
        aoffH[mi] = sb + K1_AH + base;
        aoffL[mi] = sb + K1_AL + base;
    }
    const uint4* __restrict__ fv = g_wfrag + wv * 2048 + lane;
    const uint4* __restrict__ fg = g_wfrag + wg * 2048 + lane;
    const int pbase = wn >> 4;

    float accV[2][4][4] = {};
    float accG[PAIR ? 2 : 1][4][4] = {};

    #pragma unroll
    for (int kc = 0; kc < 8; ++kc) {
        uint32_t AH[2][4], AL[2][4];
        #pragma unroll
        for (int mi = 0; mi < 2; ++mi) {
            ldm4(AH[mi], aoffH[mi] + kc*32);
            ldm4(AL[mi], aoffL[mi] + kc*32);
        }
        #pragma unroll
        for (int p4 = 0; p4 < 2; ++p4) {
            const int fidx = (kc*8 + pbase + p4) * 32;
            const uint4 bv4 = fv[fidx];
            uint4 bg4;
            if (PAIR) bg4 = fg[fidx];
            #pragma unroll
            for (int ns = 0; ns < 2; ++ns) {
                const int ni = p4*2 + ns;
                const uint32_t v0 = ns ? bv4.z : bv4.x, v1 = ns ? bv4.w : bv4.y;
                #pragma unroll
                for (int mi = 0; mi < 2; ++mi) {
                    mma_f16(accV[mi][ni], AH[mi], v0, v1);
                    mma_f16(accV[mi][ni], AL[mi], v0, v1);
                }
                if (PAIR) {
                    const uint32_t g0 = ns ? bg4.z : bg4.x, g1 = ns ? bg4.w : bg4.y;
                    #pragma unroll
                    for (int mi = 0; mi < 2; ++mi) {
                        mma_f16(accG[mi][ni], AH[mi], g0, g1);
                        mma_f16(accG[mi][ni], AL[mi], g0, g1);
                    }
                }
            }
        }
    }

    float*    stagef = (float*)(sm1 + K1_ST);
    uint32_t* stageu = (uint32_t*)(sm1 + K1_ST);
    const float* mask_s = (const float*)(sm1 + K1_MS);

    #pragma unroll
    for (int mi = 0; mi < 2; ++mi)
        #pragma unroll
        for (int ni = 0; ni < 4; ++ni) {
            const int m0 = wm + mi*16 + (lane >> 2);
            const int n  = wn + ni*8 + (lane & 3)*2;
            const float b0 = __ldg(bv + n), b1 = __ldg(bv + n + 1);
            float* a = accV[mi][ni];
            if (PAIR) {
                const float c0 = __ldg(bg + n), c1 = __ldg(bg + n + 1);
                const float* gacc = accG[mi][ni];
                const float mk0 = mask_s[m0], mk1 = mask_s[m0 + 8];
                stageu[ m0   *129 + n    ] = split_pack((a[0]+b0)*mk0*sigmoidf_(gacc[0]+c0));
                stageu[ m0   *129 + n + 1] = split_pack((a[1]+b1)*mk0*sigmoidf_(gacc[1]+c1));
                stageu[(m0+8)*129 + n    ] = split_pack((a[2]+b0)*mk1*sigmoidf_(gacc[2]+c0));
                stageu[(m0+8)*129 + n + 1] = split_pack((a[3]+b1)*mk1*sigmoidf_(gacc[3]+c1));
            } else {
                stagef[ m0   *129 + n    ] = sigmoidf_(a[0] + b0);
                stagef[ m0   *129 + n + 1] = sigmoidf_(a[1] + b1);
                stagef[(m0+8)*129 + n    ] = sigmoidf_(a[2] + b0);
                stagef[(m0+8)*129 + n + 1] = sigmoidf_(a[3] + b1);
            }
        }
    __syncthreads();

    if (MODE == 0) {
        // left: hi and lo slabs
        #pragma unroll
        for (int it = 0; it < 8; ++it) {
            const int idx = it * 256 + tid;        // 2048 = 128c x 16 row-quads
            const int c  = idx >> 4;
            const int rq = (idx & 15) * 4;
            const uint32_t u0 = stageu[(rq  )*129 + c];
            const uint32_t u1 = stageu[(rq+1)*129 + c];
            const uint32_t u2 = stageu[(rq+2)*129 + c];
            const uint32_t u3 = stageu[(rq+3)*129 + c];
            uint2 hh, ll;
            hh.x = (u0 & 0xffffu) | (u1 << 16);
            hh.y = (u2 & 0xffffu) | (u3 << 16);
            ll.x = (u0 >> 16) | (u1 & 0xffff0000u);
            ll.y = (u2 >> 16) | (u3 & 0xffff0000u);
            const size_t addr = (size_t)c * NN + gbase + rq;
            *(uint2*)(dst_h + addr) = hh;
            *(uint2*)(dst_l + addr) = ll;
        }
    } else if (MODE == 1) {
        // right: single fp16 (hi part)
        #pragma unroll
        for (int it = 0; it < 8; ++it) {
            const int idx = it * 256 + tid;
            const int c  = idx >> 4;
            const int rq = (idx & 15) * 4;
            const uint32_t u0 = stageu[(rq  )*129 + c];
            const uint32_t u1 = stageu[(rq+1)*129 + c];
            const uint32_t u2 = stageu[(rq+2)*129 + c];
            const uint32_t u3 = stageu[(rq+3)*129 + c];
            uint2 o;
            o.x = (u0 & 0xffffu) | ((u1 & 0xffffu) << 16);
            o.y = (u2 & 0xffffu) | ((u3 & 0xffffu) << 16);
            *(uint2*)(dst_h + (size_t)c * NN + gbase + rq) = o;
        }
    } else {
        #pragma unroll
        for (int it = 0; it < 8; ++it) {
            const int idx = it * 256 + tid;
            const int c  = idx >> 4;
            const int rq = (idx & 15) * 4;
            __half2 a = __floats2half2_rn(stagef[(rq  )*129 + c], stagef[(rq+1)*129 + c]);
            __half2 b = __floats2half2_rn(stagef[(rq+2)*129 + c], stagef[(rq+3)*129 + c]);
            uint2 o;
            *(__half2*)&o.x = a;
            *(__half2*)&o.y = b;
            *(uint2*)(dst_h + (size_t)c * NN + gbase + rq) = o;
        }
    }
    __syncthreads();
}

__global__ __launch_bounds__(256, 2) void ln_proj_mma_kernel(
    const float* __restrict__ x,   const float* __restrict__ msk,
    const float* __restrict__ nsc, const float* __restrict__ nbi,
    const float* __restrict__ bl,  const float* __restrict__ br,
    const float* __restrict__ blg, const float* __restrict__ brg,
    const float* __restrict__ bog)
{
    extern __shared__ __align__(16) char sm1[];
    const int tid  = threadIdx.x;
    const int lane = tid & 31;
    const int wid  = tid >> 5;
    const int n2   = blockIdx.x & 511;
    const int n1b  = (blockIdx.x >> 9) << 6;
    const uint32_t sb = smem_u32(sm1);

    {
        const int row = tid >> 2, sub = tid & 3;
        const float4* xr = reinterpret_cast<const float4*>(
                               x + ((size_t)(n1b + row) * 512 + n2) * DD) + sub * 8;
        float4 v[8];
        float s = 0.f, ss = 0.f;
        #pragma unroll
        for (int q = 0; q < 8; ++q) {
            v[q] = xr[q];
            s  += v[q].x + v[q].y + v[q].z + v[q].w;
            ss += v[q].x*v[q].x + v[q].y*v[q].y + v[q].z*v[q].z + v[q].w*v[q].w;
        }
        s  += __shfl_xor_sync(0xffffffffu, s, 1);
        ss += __shfl_xor_sync(0xffffffffu, ss, 1);
        s  += __shfl_xor_sync(0xffffffffu, s, 2);
        ss += __shfl_xor_sync(0xffffffffu, ss, 2);
        const float mu   = s * (1.f/128.f);
        const float var  = ss * (1.f/128.f) - mu*mu;
        const float rstd = rsqrtf(var + 1e-6f);
        #pragma unroll
        for (int q = 0; q < 8; ++q) {
            const int d0 = sub*32 + q*4;
            float a0 = (v[q].x - mu)*rstd*__ldg(&nsc[d0+0]) + __ldg(&nbi[d0+0]);
            float a1 = (v[q].y - mu)*rstd*__ldg(&nsc[d0+1]) + __ldg(&nbi[d0+1]);
            float a2 = (v[q].z - mu)*rstd*__ldg(&nsc[d0+2]) + __ldg(&nbi[d0+2]);
            float a3 = (v[q].w - mu)*rstd*__ldg(&nsc[d0+3]) + __ldg(&nbi[d0+3]);
            uint32_t p0 = split_pack(a0), p1 = split_pack(a1);
            uint32_t p2 = split_pack(a2), p3 = split_pack(a3);
            uint2 hw, lw;
            hw.x = (p0 & 0xffffu) | (p1 << 16);
            hw.y = (p2 & 0xffffu) | (p3 << 16);
            lw.x = (p0 >> 16) | (p1 & 0xffff0000u);
            lw.y = (p2 >> 16) | (p3 & 0xffff0000u);
            *(uint2*)(sm1 + K1_AH + row*272 + d0*2) = hw;
            *(uint2*)(sm1 + K1_AL + row*272 + d0*2) = lw;
        }
        if (sub == 0)
            ((float*)(sm1 + K1_MS))[row] = msk[n1b + row] * msk[n2];
    }
    __syncthreads();

    const int wm = (wid & 1) * 32;
    const int wn = (wid >> 1) * 32;
    const size_t gbase = (size_t)n2 * 512 + n1b;

    k1_pass2<0>(sm1, sb, 1, 0, bl,  blg, tid, lane, wm, wn,
                g_ab, g_ab + ARRSZ, gbase);
    k1_pass2<1>(sm1, sb, 3, 2, br,  brg, tid, lane, wm, wn,
                g_ab + 2*(size_t)ARRSZ, 0, gbase);
    k1_pass2<2>(sm1, sb, 4, 4, bog, bog, tid, lane, wm, wn, g_og, 0, gbase);
}

// ---------------------------------------------------------------------------
// Kernel 2: einsum via mma.sync fp16 2-split. 128x64 tiles,
// cp.async 3-stage ring, ONE sync per K-iteration, 2 CTAs/SM.
// A = left hi/lo (2 slabs), B = right single fp16 (1 slab).
// ---------------------------------------------------------------------------
#define E3_STAGE 25600
#define E3_SMEM  76800

__global__ __launch_bounds__(256, 2) void einsum_mma_kernel()
{
    extern __shared__ __align__(16) char esm[];
    const int tid  = threadIdx.x;
    const int lane = tid & 31;
    const int wid  = tid >> 5;
    const int d    = blockIdx.y;
    const int i0   = (blockIdx.x & 3) * 128;
    const int j0   = (blockIdx.x >> 2) * 64;
    const uint32_t sbm = smem_u32(esm);

    const __half* __restrict__ base = g_ab + (size_t)d * NN;

    // 5 transfers per chunk: AH 2x256, AL 2x256, B 1x256 (16B each)
    uint32_t goff[5], soff[5];
    #pragma unroll
    for (int it = 0; it < 5; ++it) {
        int arr, rem;
        if (it < 4) { arr = it >> 1; rem = (it & 1) * 256 + tid; }
        else        { arr = 2;       rem = tid; }
        const int row = rem >> 2, seg = rem & 3;
        const int r0 = (arr < 2) ? i0 : j0;
        const uint32_t ab = (arr == 0) ? 0u : (arr == 1) ? 10240u : 20480u;
        goff[it] = (uint32_t)(arr * ARRSZ) + (uint32_t)((r0 + row)*512 + seg*8);
        soff[it] = ab + (uint32_t)(row*80 + seg*16);
    }

    const int g = lane >> 3, r = lane & 7;
    const int wm = (wid & 3) * 32;
    const int wn = (wid >> 2) * 32;
    uint32_t aoff[2][2], boff[2];
    #pragma unroll
    for (int mi = 0; mi < 2; ++mi) {
        const uint32_t bse = (uint32_t)((wm + mi*16 + r + (g&1)*8)*80 + ((g>>1)*8)*2);
        aoff[0][mi] = sbm + bse;
        aoff[1][mi] = sbm + 10240 + bse;
    }
    #pragma unroll
    for (int p = 0; p < 2; ++p) {
        const uint32_t bse = (uint32_t)((wn + p*16 + r + (g>>1)*8)*80 + ((g&1)*8)*2);
        boff[p] = sbm + 20480 + bse;
    }

    float acc[2][4][4] = {};

    #pragma unroll
    for (int it = 0; it < 5; ++it)
        CPASYNC16(sbm + soff[it], base + goff[it]);
    CPCOMMIT();
    #pragma unroll
    for (int it = 0; it < 5; ++it)
        CPASYNC16(sbm + E3_STAGE + soff[it], base + goff[it] + 32);
    CPCOMMIT();

    #pragma unroll 1
    for (int kc = 0; kc < 16; ++kc) {
        if (kc < 15) { CPWAIT1(); } else { CPWAIT0(); }
        __syncthreads();

        if (kc < 14) {
            const uint32_t nstg = (uint32_t)((kc + 2) % 3) * E3_STAGE;
            const int kb = (kc + 2) * 32;
            #pragma unroll
            for (int it = 0; it < 5; ++it)
                CPASYNC16(sbm + nstg + soff[it], base + goff[it] + kb);
            CPCOMMIT();
        }

        const uint32_t stg = (uint32_t)(kc % 3) * E3_STAGE;
        #pragma unroll
        for (int ks2 = 0; ks2 < 2; ++ks2) {
            const uint32_t off = stg + (uint32_t)ks2 * 32;
            uint32_t AH[2][4], AL[2][4], B[2][4];
            #pragma unroll
            for (int mi = 0; mi < 2; ++mi) {
                ldm4(AH[mi], aoff[0][mi] + off);
                ldm4(AL[mi], aoff[1][mi] + off);
            }
            #pragma unroll
            for (int p = 0; p < 2; ++p)
                ldm4(B[p], boff[p] + off);
            #pragma unroll
            for (int mi = 0; mi < 2; ++mi)
                #pragma unroll
                for (int ni = 0; ni < 4; ++ni) {
                    const int p = ni >> 1, h = (ni & 1) * 2;
                    mma_f16(acc[mi][ni], AH[mi], B[p][h], B[p][h+1]);
                    mma_f16(acc[mi][ni], AL[mi], B[p][h], B[p][h+1]);
                }
        }
    }
    __syncthreads();

    float* smT = (float*)esm;   // [64][132]
    #pragma unroll
    for (int mi = 0; mi < 2; ++mi)
        #pragma unroll
        for (int ni = 0; ni < 4; ++ni) {
            const int m = wm + mi*16 + (lane >> 2);
            const int j = wn + ni*8 + (lane & 3)*2;
            smT[(j  )*132 + m    ] = acc[mi][ni][0];
            smT[(j+1)*132 + m    ] = acc[mi][ni][1];
            smT[(j  )*132 + m + 8] = acc[mi][ni][2];
            smT[(j+1)*132 + m + 8] = acc[mi][ni][3];
        }
    __syncthreads();

    __half* gm = g_mix + (size_t)d * NN;
    #pragma unroll
    for (int it = 0; it < 8; ++it) {
        const int idx = it*256 + tid;
        const int j = idx >> 5, c4 = idx & 31;
        __half2 h0 = __floats2half2_rn(smT[j*132 + c4*4 + 0], smT[j*132 + c4*4 + 1]);
        __half2 h1 = __floats2half2_rn(smT[j*132 + c4*4 + 2], smT[j*132 + c4*4 + 3]);
        uint2 o;
        *(__half2*)&o.x = h0;
        *(__half2*)&o.y = h1;
        *(uint2*)(gm + (size_t)(j0 + j)*512 + i0 + c4*4) = o;
    }
}

// ---------------------------------------------------------------------------
// Kernel 3: out-LN (over d) * out_gate, then @ W_out + b_out — fp16 2-split.
// g_mix fp16 read twice (2nd hits L2). smem 36.9KB -> 4 CTAs/SM.
// ---------------------------------------------------------------------------
#define O_AH    0
#define O_AL    17408
#define O_RED   34816
#define O_SMEM  36864

__global__ __launch_bounds__(256, 4) void out_mma_kernel(
    const float* __restrict__ gs, const float* __restrict__ gb,
    const float* __restrict__ bout, float* __restrict__ out)
{
    extern __shared__ __align__(16) char sm3[];
    const int tid  = threadIdx.x;
    const int lane = tid & 31;
    const int wid  = tid >> 5;
    const int rt0  = blockIdx.x * 64;
    const int j    = rt0 >> 9;
    const int ibase = rt0 & 511;
    const uint32_t sb = smem_u32(sm3);

    float* red = (float*)(sm3 + O_RED);

    const int rt_l = tid & 63;
    const int qtr  = tid >> 6;
    const int d0   = qtr * 32;

    float s = 0.f, q = 0.f;
    #pragma unroll 8
    for (int dd = d0; dd < d0 + 32; ++dd) {
        float v = __half2float(g_mix[(size_t)dd*NN + rt0 + rt_l]);
        s += v; q += v*v;
    }
    red[qtr*64 + rt_l]       = s;
    red[256 + qtr*64 + rt_l] = q;
    __syncthreads();
    const float S = red[rt_l] + red[64 + rt_l] + red[128 + rt_l] + red[192 + rt_l];
    const float Q = red[256 + rt_l] + red[320 + rt_l] + red[384 + rt_l] + red[448 + rt_l];
    const float mu   = S * (1.f/128.f);
    const float rstd = rsqrtf(Q * (1.f/128.f) - mu*mu + 1e-6f);

    #pragma unroll 4
    for (int dd = d0; dd < d0 + 32; dd += 2) {
        float v0 = __half2float(g_mix[(size_t) dd     *NN + rt0 + rt_l]);
        float v1 = __half2float(g_mix[(size_t)(dd + 1)*NN + rt0 + rt_l]);
        float o0 = __half2float(g_og[(size_t) dd     *NN + rt0 + rt_l]);
        float o1 = __half2float(g_og[(size_t)(dd + 1)*NN + rt0 + rt_l]);
        float g0 = ((v0 - mu)*rstd*__ldg(gs+dd)   + __ldg(gb+dd))   * o0;
        float g1 = ((v1 - mu)*rstd*__ldg(gs+dd+1) + __ldg(gb+dd+1)) * o1;
        uint32_t p0 = split_pack(g0), p1 = split_pack(g1);
        *(uint32_t*)(sm3 + O_AH + rt_l*272 + dd*2) = (p0 & 0xffffu) | (p1 << 16);
        *(uint32_t*)(sm3 + O_AL + rt_l*272 + dd*2) = (p0 >> 16) | (p1 & 0xffff0000u);
    }
    __syncthreads();

    const int g = lane >> 3, r = lane & 7;
    const int wm = (wid & 1) * 32;
    const int wn = (wid >> 1) * 32;
    uint32_t aoffH[2], aoffL[2];
    #pragma unroll
    for (int mi = 0; mi < 2; ++mi) {
        const uint32_t bse = (uint32_t)((wm + mi*16 + r + (g&1)*8) * 272 + ((g>>1)*8)*2);
        aoffH[mi] = sb + O_AH + bse;
        aoffL[mi] = sb + O_AL + bse;
    }
    const uint4* __restrict__ fw = g_wfrag + 5 * 2048 + lane;
    const int pbase = wn >> 4;

    float acc[2][4][4] = {};
    #pragma unroll
    for (int kc = 0; kc < 8; ++kc) {
        uint32_t AH[2][4], AL[2][4];
        #pragma unroll
        for (int mi = 0; mi < 2; ++mi) {
            ldm4(AH[mi], aoffH[mi] + kc*32);
            ldm4(AL[mi], aoffL[mi] + kc*32);
        }
        #pragma unroll
        for (int p4 = 0; p4 < 2; ++p4) {
            const uint4 bh = fw[(kc*8 + pbase + p4) * 32];
            #pragma unroll
            for (int ns = 0; ns < 2; ++ns) {
                const int ni = p4*2 + ns;
                const uint32_t h0 = ns ? bh.z : bh.x, h1 = ns ? bh.w : bh.y;
                #pragma unroll
                for (int mi = 0; mi < 2; ++mi) {
                    mma_f16(acc[mi][ni], AH[mi], h0, h1);
                    mma_f16(acc[mi][ni], AL[mi], h0, h1);
                }
            }
        }
    }
    __syncthreads();   // A reads done; reuse AH/AL region as out stage [64][132]

    float* stagef = (float*)(sm3 + O_AH);
    #pragma unroll
    for (int mi = 0; mi < 2; ++mi)
        #pragma unroll
        for (int ni = 0; ni < 4; ++ni) {
            const int m0 = wm + mi*16 + (lane >> 2);
            const int n  = wn + ni*8 + (lane & 3)*2;
            const float b0 = __ldg(bout + n), b1 = __ldg(bout + n + 1);
            stagef[ m0   *132 + n    ] = acc[mi][ni][0] + b0;
            stagef[ m0   *132 + n + 1] = acc[mi][ni][1] + b1;
            stagef[(m0+8)*132 + n    ] = acc[mi][ni][2] + b0;
            stagef[(m0+8)*132 + n + 1] = acc[mi][ni][3] + b1;
        }
    __syncthreads();

    #pragma unroll
    for (int it = 0; it < 8; ++it) {
        const int idx = it * 256 + tid;
        const int row = idx >> 5, c4 = idx & 31;
        float4 v;
        v.x = stagef[row*132 + c4*4 + 0];
        v.y = stagef[row*132 + c4*4 + 1];
        v.z = stagef[row*132 + c4*4 + 2];
        v.w = stagef[row*132 + c4*4 + 3];
        *reinterpret_cast<float4*>(
            out + ((size_t)(ibase + row)*512 + j)*DD + c4*4) = v;
    }
}

// ---------------------------------------------------------------------------
extern "C" void kernel_launch(void* const* d_in, const int* in_sizes, int n_in,
                              void* d_out, int out_size)
{
    const float* x    = (const float*)d_in[0];
    const float* mskp = (const float*)d_in[1];
    const float* nsc  = (const float*)d_in[2];
    const float* nbi  = (const float*)d_in[3];
    const float* Wl   = (const float*)d_in[4];
    const float* bl   = (const float*)d_in[5];
    const float* Wr   = (const float*)d_in[6];
    const float* br   = (const float*)d_in[7];
    const float* Wlg  = (const float*)d_in[8];
    const float* blg  = (const float*)d_in[9];
    const float* Wrg  = (const float*)d_in[10];
    const float* brg  = (const float*)d_in[11];
    const float* Wog  = (const float*)d_in[12];
    const float* bog  = (const float*)d_in[13];
    const float* gs   = (const float*)d_in[14];
    const float* gb   = (const float*)d_in[15];
    const float* Wout = (const float*)d_in[16];
    const float* bout = (const float*)d_in[17];
    float* out = (float*)d_out;

    cudaFuncSetAttribute(einsum_mma_kernel,
                         cudaFuncAttributeMaxDynamicSharedMemorySize, E3_SMEM);
    cudaFuncSetAttribute(ln_proj_mma_kernel,
                         cudaFuncAttributeMaxDynamicSharedMemorySize, K1_SMEM);
    cudaFuncSetAttribute(out_mma_kernel,
                         cudaFuncAttributeMaxDynamicSharedMemorySize, O_SMEM);

    wprep_kernel<<<6, 256>>>(Wlg, Wl, Wrg, Wr, Wog, Wout);
    ln_proj_mma_kernel<<<4096, 256, K1_SMEM>>>(x, mskp, nsc, nbi,
                                               bl, br, blg, brg, bog);
    einsum_mma_kernel<<<dim3(32, 128), 256, E3_SMEM>>>();
    out_mma_kernel<<<4096, 256, O_SMEM>>>(gs, gb, bout, out);
}

// round 13
// speedup vs baseline: 1.8182x; 1.2109x over previous
#include <cuda_runtime.h>
#include <cuda_bf16.h>
#include <cuda_fp16.h>
#include <math.h>
#include <stdint.h>

// Problem constants
#define NTOK 512
#define DD   128
#define NN   (NTOK*NTOK)

// Scratch (static __device__ arrays — no allocation allowed)
//   g_ab[arr][c][row*512+k] fp16: arr 0=left 1=right (single-rounded)
//   g_og  [c][j*512+i] fp16 sigmoid(out-gate)
//   g_mix [d][j*512+i] einsum result fp16
//   g_wfrag[w][kc][p][lane] uint4 — fp16 B-fragment-ready weights
__device__ __half        g_ab [67108864];
__device__ __half        g_og [33554432];
__device__ __half        g_mix[33554432];
__device__ __align__(16) uint4 g_wfrag[6 * 2048];

#define ARRSZ (128*NN)

// ---------------------------------------------------------------------------
// helpers
// ---------------------------------------------------------------------------
__device__ __forceinline__ uint32_t smem_u32(const void* p) {
    uint32_t a;
    asm("{ .reg .u64 t; cvta.to.shared.u64 t, %1; cvt.u32.u64 %0, t; }"
        : "=r"(a) : "l"(p));
    return a;
}

__device__ __forceinline__ void ldm4(uint32_t r[4], uint32_t addr) {
    asm volatile("ldmatrix.sync.aligned.m8n8.x4.shared.b16 {%0,%1,%2,%3}, [%4];"
                 : "=r"(r[0]), "=r"(r[1]), "=r"(r[2]), "=r"(r[3]) : "r"(addr));
}

__device__ __forceinline__ void mma_f16(float acc[4], const uint32_t a[4],
                                        uint32_t b0, uint32_t b1) {
    asm volatile(
        "mma.sync.aligned.m16n8k16.row.col.f32.f16.f16.f32 "
        "{%0,%1,%2,%3}, {%4,%5,%6,%7}, {%8,%9}, {%0,%1,%2,%3};"
        : "+f"(acc[0]), "+f"(acc[1]), "+f"(acc[2]), "+f"(acc[3])
        : "r"(a[0]), "r"(a[1]), "r"(a[2]), "r"(a[3]), "r"(b0), "r"(b1));
}

#define CPASYNC16(dst, src) \
    asm volatile("cp.async.cg.shared.global [%0], [%1], 16;" \
                 :: "r"(dst), "l"(src) : "memory")
#define CPCOMMIT() asm volatile("cp.async.commit_group;" ::: "memory")
#define CPWAIT1()  asm volatile("cp.async.wait_group 1;" ::: "memory")
#define CPWAIT0()  asm volatile("cp.async.wait_group 0;" ::: "memory")

__device__ __forceinline__ float sigmoidf_(float z) {
    return 1.f / (1.f + expf(-z));
}

// fp16 hi/lo split: low16 = hi fp16, high16 = lo fp16
__device__ __forceinline__ uint32_t split_pack(float v) {
    __half h = __float2half_rn(v);
    __half l = __float2half_rn(v - __half2float(h));
    uint16_t hu = *(uint16_t*)&h, lu = *(uint16_t*)&l;
    return (uint32_t)hu | ((uint32_t)lu << 16);
}

// ---------------------------------------------------------------------------
// Kernel 0: weights -> fp16 B-fragment layout, register-ready for mma.sync.
// ---------------------------------------------------------------------------
__global__ void wprep_kernel(const float* __restrict__ W0, const float* __restrict__ W1,
                             const float* __restrict__ W2, const float* __restrict__ W3,
                             const float* __restrict__ W4, const float* __restrict__ W5)
{
    const float* W = (blockIdx.x == 0) ? W0 : (blockIdx.x == 1) ? W1 :
                     (blockIdx.x == 2) ? W2 : (blockIdx.x == 3) ? W3 :
                     (blockIdx.x == 4) ? W4 : W5;
    uint4* dst = g_wfrag + blockIdx.x * 2048;
    for (int idx = threadIdx.x; idx < 2048; idx += 256) {
        const int lane = idx & 31;
        const int p    = (idx >> 5) & 7;
        const int kc   = idx >> 8;
        const int nf = p * 16 + (lane >> 2);
        const int k0 = kc * 16 + 2 * (lane & 3);
        uint16_t e[8];
        #pragma unroll
        for (int q = 0; q < 8; ++q) {
            const int k = k0 + (q & 1) + ((q >> 1) & 1) * 8;
            const int n = nf + (q >> 2) * 8;
            __half h = __float2half_rn(W[k * 128 + n]);
            e[q] = *(uint16_t*)&h;
        }
        uint4 o;
        o.x = (uint32_t)e[0] | ((uint32_t)e[1] << 16);
        o.y = (uint32_t)e[2] | ((uint32_t)e[3] << 16);
        o.z = (uint32_t)e[4] | ((uint32_t)e[5] << 16);
        o.w = (uint32_t)e[6] | ((uint32_t)e[7] << 16);
        dst[idx] = o;
    }
}

// ---------------------------------------------------------------------------
// Kernel 1: LayerNorm + 5 projections (fp16 MMA, fused value+gate).
// Value MMA uses A hi+lo (2 MMAs); gate MMA uses A hi only (1 MMA).
// 64-row blocks, 8 warps 2m x 4n, 2 CTAs/SM.
// MODE: 1 = value+gate (store gated value single fp16), 2 = out-gate
// ---------------------------------------------------------------------------
#define K1_AH   0
#define K1_AL   17408
#define K1_ST   34816
#define K1_MS   67840
#define K1_SMEM 68096

template<int MODE>
__device__ __forceinline__ void k1_pass2(
    char* sm1, uint32_t sb, int wv, int wg,
    const float* __restrict__ bv, const float* __restrict__ bg,
    int tid, int lane, int wm, int wn,
    __half* dst, size_t gbase)
{
    constexpr bool PAIR = (MODE == 1);
    const int g = lane >> 3, r = lane & 7;
    uint32_t aoffH[2], aoffL[2];
    #pragma unroll
    for (int mi = 0; mi < 2; ++mi) {
        const uint32_t base = (uint32_t)((wm + mi*16 + r + (g&1)*8) * 272 + ((g>>1)*8)*2);
        aoffH[mi] = sb + K1_AH + base;
        aoffL[mi] = sb + K1_AL + base;
    }
    const uint4* __restrict__ fv = g_wfrag + wv * 2048 + lane;
    const uint4* __restrict__ fg = g_wfrag + wg * 2048 + lane;
    const int pbase = wn >> 4;

    float accV[2][4][4] = {};
    float accG[PAIR ? 2 : 1][4][4] = {};

    #pragma unroll
    for (int kc = 0; kc < 8; ++kc) {
        uint32_t AH[2][4], AL[2][4];
        #pragma unroll
        for (int mi = 0; mi < 2; ++mi) {
            ldm4(AH[mi], aoffH[mi] + kc*32);
            ldm4(AL[mi], aoffL[mi] + kc*32);
        }
        #pragma unroll
        for (int p4 = 0; p4 < 2; ++p4) {
            const int fidx = (kc*8 + pbase + p4) * 32;
            const uint4 bv4 = fv[fidx];
            uint4 bg4;
            if (PAIR) bg4 = fg[fidx];
            #pragma unroll
            for (int ns = 0; ns < 2; ++ns) {
                const int ni = p4*2 + ns;
                const uint32_t v0 = ns ? bv4.z : bv4.x, v1 = ns ? bv4.w : bv4.y;
                #pragma unroll
                for (int mi = 0; mi < 2; ++mi) {
                    mma_f16(accV[mi][ni], AH[mi], v0, v1);
                    mma_f16(accV[mi][ni], AL[mi], v0, v1);
                }
                if (PAIR) {
                    const uint32_t g0 = ns ? bg4.z : bg4.x, g1 = ns ? bg4.w : bg4.y;
                    #pragma unroll
                    for (int mi = 0; mi < 2; ++mi)
                        mma_f16(accG[mi][ni], AH[mi], g0, g1);
                }
            }
        }
    }

    float* stagef = (float*)(sm1 + K1_ST);
    const float* mask_s = (const float*)(sm1 + K1_MS);

    #pragma unroll
    for (int mi = 0; mi < 2; ++mi)
        #pragma unroll
        for (int ni = 0; ni < 4; ++ni) {
            const int m0 = wm + mi*16 + (lane >> 2);
            const int n  = wn + ni*8 + (lane & 3)*2;
            const float b0 = __ldg(bv + n), b1 = __ldg(bv + n + 1);
            float* a = accV[mi][ni];
            if (PAIR) {
                const float c0 = __ldg(bg + n), c1 = __ldg(bg + n + 1);
                const float* gacc = accG[mi][ni];
                const float mk0 = mask_s[m0], mk1 = mask_s[m0 + 8];
                stagef[ m0   *129 + n    ] = (a[0]+b0)*mk0*sigmoidf_(gacc[0]+c0);
                stagef[ m0   *129 + n + 1] = (a[1]+b1)*mk0*sigmoidf_(gacc[1]+c1);
                stagef[(m0+8)*129 + n    ] = (a[2]+b0)*mk1*sigmoidf_(gacc[2]+c0);
                stagef[(m0+8)*129 + n + 1] = (a[3]+b1)*mk1*sigmoidf_(gacc[3]+c1);
            } else {
                stagef[ m0   *129 + n    ] = sigmoidf_(a[0] + b0);
                stagef[ m0   *129 + n + 1] = sigmoidf_(a[1] + b1);
                stagef[(m0+8)*129 + n    ] = sigmoidf_(a[2] + b0);
                stagef[(m0+8)*129 + n + 1] = sigmoidf_(a[3] + b1);
            }
        }
    __syncthreads();

    #pragma unroll
    for (int it = 0; it < 8; ++it) {
        const int idx = it * 256 + tid;        // 2048 = 128c x 16 row-quads
        const int c  = idx >> 4;
        const int rq = (idx & 15) * 4;
        __half2 a = __floats2half2_rn(stagef[(rq  )*129 + c], stagef[(rq+1)*129 + c]);
        __half2 b = __floats2half2_rn(stagef[(rq+2)*129 + c], stagef[(rq+3)*129 + c]);
        uint2 o;
        *(__half2*)&o.x = a;
        *(__half2*)&o.y = b;
        *(uint2*)(dst + (size_t)c * NN + gbase + rq) = o;
    }
    __syncthreads();
}

__global__ __launch_bounds__(256, 2) void ln_proj_mma_kernel(
    const float* __restrict__ x,   const float* __restrict__ msk,
    const float* __restrict__ nsc, const float* __restrict__ nbi,
    const float* __restrict__ bl,  const float* __restrict__ br,
    const float* __restrict__ blg, const float* __restrict__ brg,
    const float* __restrict__ bog)
{
    extern __shared__ __align__(16) char sm1[];
    const int tid  = threadIdx.x;
    const int lane = tid & 31;
    const int wid  = tid >> 5;
    const int n2   = blockIdx.x & 511;
    const int n1b  = (blockIdx.x >> 9) << 6;
    const uint32_t sb = smem_u32(sm1);

    {
        const int row = tid >> 2, sub = tid & 3;
        const float4* xr = reinterpret_cast<const float4*>(
                               x + ((size_t)(n1b + row) * 512 + n2) * DD) + sub * 8;
        float4 v[8];
        float s = 0.f, ss = 0.f;
        #pragma unroll
        for (int q = 0; q < 8; ++q) {
            v[q] = xr[q];
            s  += v[q].x + v[q].y + v[q].z + v[q].w;
            ss += v[q].x*v[q].x + v[q].y*v[q].y + v[q].z*v[q].z + v[q].w*v[q].w;
        }
        s  += __shfl_xor_sync(0xffffffffu, s, 1);
        ss += __shfl_xor_sync(0xffffffffu, ss, 1);
        s  += __shfl_xor_sync(0xffffffffu, s, 2);
        ss += __shfl_xor_sync(0xffffffffu, ss, 2);
        const float mu   = s * (1.f/128.f);
        const float var  = ss * (1.f/128.f) - mu*mu;
        const float rstd = rsqrtf(var + 1e-6f);
        #pragma unroll
        for (int q = 0; q < 8; ++q) {
            const int d0 = sub*32 + q*4;
            float a0 = (v[q].x - mu)*rstd*__ldg(&nsc[d0+0]) + __ldg(&nbi[d0+0]);
            float a1 = (v[q].y - mu)*rstd*__ldg(&nsc[d0+1]) + __ldg(&nbi[d0+1]);
            float a2 = (v[q].z - mu)*rstd*__ldg(&nsc[d0+2]) + __ldg(&nbi[d0+2]);
            float a3 = (v[q].w - mu)*rstd*__ldg(&nsc[d0+3]) + __ldg(&nbi[d0+3]);
            uint32_t p0 = split_pack(a0), p1 = split_pack(a1);
            uint32_t p2 = split_pack(a2), p3 = split_pack(a3);
            uint2 hw, lw;
            hw.x = (p0 & 0xffffu) | (p1 << 16);
            hw.y = (p2 & 0xffffu) | (p3 << 16);
            lw.x = (p0 >> 16) | (p1 & 0xffff0000u);
            lw.y = (p2 >> 16) | (p3 & 0xffff0000u);
            *(uint2*)(sm1 + K1_AH + row*272 + d0*2) = hw;
            *(uint2*)(sm1 + K1_AL + row*272 + d0*2) = lw;
        }
        if (sub == 0)
            ((float*)(sm1 + K1_MS))[row] = msk[n1b + row] * msk[n2];
    }
    __syncthreads();

    const int wm = (wid & 1) * 32;
    const int wn = (wid >> 1) * 32;
    const size_t gbase = (size_t)n2 * 512 + n1b;

    k1_pass2<1>(sm1, sb, 1, 0, bl,  blg, tid, lane, wm, wn, g_ab,         gbase);
    k1_pass2<1>(sm1, sb, 3, 2, br,  brg, tid, lane, wm, wn, g_ab + ARRSZ, gbase);
    k1_pass2<2>(sm1, sb, 4, 4, bog, bog, tid, lane, wm, wn, g_og,         gbase);
}

// ---------------------------------------------------------------------------
// Kernel 2: einsum via mma.sync fp16 single x single (1 MMA per k16-step).
// 128x64 tiles, cp.async 3-stage ring, ONE sync per K-iteration, 3 CTAs/SM.
// ---------------------------------------------------------------------------
#define E3_STAGE 15360
#define E3_SMEM  46080

__global__ __launch_bounds__(256, 3) void einsum_mma_kernel()
{
    extern __shared__ __align__(16) char esm[];
    const int tid  = threadIdx.x;
    const int lane = tid & 31;
    const int wid  = tid >> 5;
    const int d    = blockIdx.y;
    const int i0   = (blockIdx.x & 3) * 128;
    const int j0   = (blockIdx.x >> 2) * 64;
    const uint32_t sbm = smem_u32(esm);

    const __half* __restrict__ base = g_ab + (size_t)d * NN;

    // 3 transfers per chunk: A 2x256thr (128 rows), B 1x256thr (64 rows)
    uint32_t goff[3], soff[3];
    #pragma unroll
    for (int it = 0; it < 3; ++it) {
        int arr, rem;
        if (it < 2) { arr = 0; rem = it * 256 + tid; }
        else        { arr = 1; rem = tid; }
        const int row = rem >> 2, seg = rem & 3;
        const int r0 = (arr == 0) ? i0 : j0;
        const uint32_t ab = (arr == 0) ? 0u : 10240u;
        goff[it] = (uint32_t)(arr * ARRSZ) + (uint32_t)((r0 + row)*512 + seg*8);
        soff[it] = ab + (uint32_t)(row*80 + seg*16);
    }

    const int g = lane >> 3, r = lane & 7;
    const int wm = (wid & 3) * 32;
    const int wn = (wid >> 2) * 32;
    uint32_t aoff[2], boff[2];
    #pragma unroll
    for (int mi = 0; mi < 2; ++mi)
        aoff[mi] = sbm + (uint32_t)((wm + mi*16 + r + (g&1)*8)*80 + ((g>>1)*8)*2);
    #pragma unroll
    for (int p = 0; p < 2; ++p)
        boff[p] = sbm + 10240 + (uint32_t)((wn + p*16 + r + (g>>1)*8)*80 + ((g&1)*8)*2);

    float acc[2][4][4] = {};

    #pragma unroll
    for (int it = 0; it < 3; ++it)
        CPASYNC16(sbm + soff[it], base + goff[it]);
    CPCOMMIT();
    #pragma unroll
    for (int it = 0; it < 3; ++it)
        CPASYNC16(sbm + E3_STAGE + soff[it], base + goff[it] + 32);
    CPCOMMIT();

    #pragma unroll 1
    for (int kc = 0; kc < 16; ++kc) {
        if (kc < 15) { CPWAIT1(); } else { CPWAIT0(); }
        __syncthreads();

        if (kc < 14) {
            const uint32_t nstg = (uint32_t)((kc + 2) % 3) * E3_STAGE;
            const int kb = (kc + 2) * 32;
            #pragma unroll
            for (int it = 0; it < 3; ++it)
                CPASYNC16(sbm + nstg + soff[it], base + goff[it] + kb);
            CPCOMMIT();
        }

        const uint32_t stg = (uint32_t)(kc % 3) * E3_STAGE;
        #pragma unroll
        for (int ks2 = 0; ks2 < 2; ++ks2) {
            const uint32_t off = stg + (uint32_t)ks2 * 32;
            uint32_t A[2][4], B[2][4];
            #pragma unroll
            for (int mi = 0; mi < 2; ++mi)
                ldm4(A[mi], aoff[mi] + off);
            #pragma unroll
            for (int p = 0; p < 2; ++p)
                ldm4(B[p], boff[p] + off);
            #pragma unroll
            for (int mi = 0; mi < 2; ++mi)
                #pragma unroll
                for (int ni = 0; ni < 4; ++ni) {
                    const int p = ni >> 1, h = (ni & 1) * 2;
                    mma_f16(acc[mi][ni], A[mi], B[p][h], B[p][h+1]);
                }
        }
    }
    __syncthreads();

    float* smT = (float*)esm;   // [64][132] = 33792 < 46080
    #pragma unroll
    for (int mi = 0; mi < 2; ++mi)
        #pragma unroll
        for (int ni = 0; ni < 4; ++ni) {
            const int m = wm + mi*16 + (lane >> 2);
            const int j = wn + ni*8 + (lane & 3)*2;
            smT[(j  )*132 + m    ] = acc[mi][ni][0];
            smT[(j+1)*132 + m    ] = acc[mi][ni][1];
            smT[(j  )*132 + m + 8] = acc[mi][ni][2];
            smT[(j+1)*132 + m + 8] = acc[mi][ni][3];
        }
    __syncthreads();

    __half* gm = g_mix + (size_t)d * NN;
    #pragma unroll
    for (int it = 0; it < 8; ++it) {
        const int idx = it*256 + tid;
        const int j = idx >> 5, c4 = idx & 31;
        __half2 h0 = __floats2half2_rn(smT[j*132 + c4*4 + 0], smT[j*132 + c4*4 + 1]);
        __half2 h1 = __floats2half2_rn(smT[j*132 + c4*4 + 2], smT[j*132 + c4*4 + 3]);
        uint2 o;
        *(__half2*)&o.x = h0;
        *(__half2*)&o.y = h1;
        *(uint2*)(gm + (size_t)(j0 + j)*512 + i0 + c4*4) = o;
    }
}

// ---------------------------------------------------------------------------
// Kernel 3: out-LN (over d) * out_gate, then @ W_out + b_out — fp16 2-split A.
// g_mix fp16 read twice (2nd hits L2). smem 36.9KB -> 4 CTAs/SM.
// ---------------------------------------------------------------------------
#define O_AH    0
#define O_AL    17408
#define O_RED   34816
#define O_SMEM  36864

__global__ __launch_bounds__(256, 4) void out_mma_kernel(
    const float* __restrict__ gs, const float* __restrict__ gb,
    const float* __restrict__ bout, float* __restrict__ out)
{
    extern __shared__ __align__(16) char sm3[];
    const int tid  = threadIdx.x;
    const int lane = tid & 31;
    const int wid  = tid >> 5;
    const int rt0  = blockIdx.x * 64;
    const int j    = rt0 >> 9;
    const int ibase = rt0 & 511;
    const uint32_t sb = smem_u32(sm3);

    float* red = (float*)(sm3 + O_RED);

    const int rt_l = tid & 63;
    const int qtr  = tid >> 6;
    const int d0   = qtr * 32;

    float s = 0.f, q = 0.f;
    #pragma unroll 8
    for (int dd = d0; dd < d0 + 32; ++dd) {
        float v = __half2float(g_mix[(size_t)dd*NN + rt0 + rt_l]);
        s += v; q += v*v;
    }
    red[qtr*64 + rt_l]       = s;
    red[256 + qtr*64 + rt_l] = q;
    __syncthreads();
    const float S = red[rt_l] + red[64 + rt_l] + red[128 + rt_l] + red[192 + rt_l];
    const float Q = red[256 + rt_l] + red[320 + rt_l] + red[384 + rt_l] + red[448 + rt_l];
    const float mu   = S * (1.f/128.f);
    const float rstd = rsqrtf(Q * (1.f/128.f) - mu*mu + 1e-6f);

    #pragma unroll 4
    for (int dd = d0; dd < d0 + 32; dd += 2) {
        float v0 = __half2float(g_mix[(size_t) dd     *NN + rt0 + rt_l]);
        float v1 = __half2float(g_mix[(size_t)(dd + 1)*NN + rt0 + rt_l]);
        float o0 = __half2float(g_og[(size_t) dd     *NN + rt0 + rt_l]);
        float o1 = __half2float(g_og[(size_t)(dd + 1)*NN + rt0 + rt_l]);
        float g0 = ((v0 - mu)*rstd*__ldg(gs+dd)   + __ldg(gb+dd))   * o0;
        float g1 = ((v1 - mu)*rstd*__ldg(gs+dd+1) + __ldg(gb+dd+1)) * o1;
        uint32_t p0 = split_pack(g0), p1 = split_pack(g1);
        *(uint32_t*)(sm3 + O_AH + rt_l*272 + dd*2) = (p0 & 0xffffu) | (p1 << 16);
        *(uint32_t*)(sm3 + O_AL + rt_l*272 + dd*2) = (p0 >> 16) | (p1 & 0xffff0000u);
    }
    __syncthreads();

    const int g = lane >> 3, r = lane & 7;
    const int wm = (wid & 1) * 32;
    const int wn = (wid >> 1) * 32;
    uint32_t aoffH[2], aoffL[2];
    #pragma unroll
    for (int mi = 0; mi < 2; ++mi) {
        const uint32_t bse = (uint32_t)((wm + mi*16 + r + (g&1)*8) * 272 + ((g>>1)*8)*2);
        aoffH[mi] = sb + O_AH + bse;
        aoffL[mi] = sb + O_AL + bse;
    }
    const uint4* __restrict__ fw = g_wfrag + 5 * 2048 + lane;
    const int pbase = wn >> 4;

    float acc[2][4][4] = {};
    #pragma unroll
    for (int kc = 0; kc < 8; ++kc) {
        uint32_t AH[2][4], AL[2][4];
        #pragma unroll
        for (int mi = 0; mi < 2; ++mi) {
            ldm4(AH[mi], aoffH[mi] + kc*32);
            ldm4(AL[mi], aoffL[mi] + kc*32);
        }
        #pragma unroll
        for (int p4 = 0; p4 < 2; ++p4) {
            const uint4 bh = fw[(kc*8 + pbase + p4) * 32];
            #pragma unroll
            for (int ns = 0; ns < 2; ++ns) {
                const int ni = p4*2 + ns;
                const uint32_t h0 = ns ? bh.z : bh.x, h1 = ns ? bh.w : bh.y;
                #pragma unroll
                for (int mi = 0; mi < 2; ++mi) {
                    mma_f16(acc[mi][ni], AH[mi], h0, h1);
                    mma_f16(acc[mi][ni], AL[mi], h0, h1);
                }
            }
        }
    }
    __syncthreads();   // A reads done; reuse AH/AL region as out stage [64][132]

    float* stagef = (float*)(sm3 + O_AH);
    #pragma unroll
    for (int mi = 0; mi < 2; ++mi)
        #pragma unroll
        for (int ni = 0; ni < 4; ++ni) {
            const int m0 = wm + mi*16 + (lane >> 2);
            const int n  = wn + ni*8 + (lane & 3)*2;
            const float b0 = __ldg(bout + n), b1 = __ldg(bout + n + 1);
            stagef[ m0   *132 + n    ] = acc[mi][ni][0] + b0;
            stagef[ m0   *132 + n + 1] = acc[mi][ni][1] + b1;
            stagef[(m0+8)*132 + n    ] = acc[mi][ni][2] + b0;
            stagef[(m0+8)*132 + n + 1] = acc[mi][ni][3] + b1;
        }
    __syncthreads();

    #pragma unroll
    for (int it = 0; it < 8; ++it) {
        const int idx = it * 256 + tid;
        const int row = idx >> 5, c4 = idx & 31;
        float4 v;
        v.x = stagef[row*132 + c4*4 + 0];
        v.y = stagef[row*132 + c4*4 + 1];
        v.z = stagef[row*132 + c4*4 + 2];
        v.w = stagef[row*132 + c4*4 + 3];
        *reinterpret_cast<float4*>(
            out + ((size_t)(ibase + row)*512 + j)*DD + c4*4) = v;
    }
}

// ---------------------------------------------------------------------------
extern "C" void kernel_launch(void* const* d_in, const int* in_sizes, int n_in,
                              void* d_out, int out_size)
{
    const float* x    = (const float*)d_in[0];
    const float* mskp = (const float*)d_in[1];
    const float* nsc  = (const float*)d_in[2];
    const float* nbi  = (const float*)d_in[3];
    const float* Wl   = (const float*)d_in[4];
    const float* bl   = (const float*)d_in[5];
    const float* Wr   = (const float*)d_in[6];
    const float* br   = (const float*)d_in[7];
    const float* Wlg  = (const float*)d_in[8];
    const float* blg  = (const float*)d_in[9];
    const float* Wrg  = (const float*)d_in[10];
    const float* brg  = (const float*)d_in[11];
    const float* Wog  = (const float*)d_in[12];
    const float* bog  = (const float*)d_in[13];
    const float* gs   = (const float*)d_in[14];
    const float* gb   = (const float*)d_in[15];
    const float* Wout = (const float*)d_in[16];
    const float* bout = (const float*)d_in[17];
    float* out = (float*)d_out;

    cudaFuncSetAttribute(einsum_mma_kernel,
                         cudaFuncAttributeMaxDynamicSharedMemorySize, E3_SMEM);
    cudaFuncSetAttribute(ln_proj_mma_kernel,
                         cudaFuncAttributeMaxDynamicSharedMemorySize, K1_SMEM);
    cudaFuncSetAttribute(out_mma_kernel,
                         cudaFuncAttributeMaxDynamicSharedMemorySize, O_SMEM);

    wprep_kernel<<<6, 256>>>(Wlg, Wl, Wrg, Wr, Wog, Wout);
    ln_proj_mma_kernel<<<4096, 256, K1_SMEM>>>(x, mskp, nsc, nbi,
                                               bl, br, blg, brg, bog);
    einsum_mma_kernel<<<dim3(32, 128), 256, E3_SMEM>>>();
    out_mma_kernel<<<4096, 256, O_SMEM>>>(gs, gb, bout, out);
}